// round 13
// baseline (speedup 1.0000x reference)
#include <cuda_runtime.h>
#include <cuda_bf16.h>
#include <cstdint>

#define HID 512
#define POOL 4096
#define N_OBJ 1280
#define N_REL 16384
#define NUM_OBJ_CLS 151
#define NUM_REL_CLS 51
#define NPAD 64

// K3 tiling: M=128, 512 threads, split-K=4
#define R3_M 128
#define R3_BK 64
#define R3_SPLITK 4
#define R3_KS (POOL / R3_SPLITK)   // 1024
#define R3_NCH (R3_KS / R3_BK)     // 16
#define R3_STAGE 49152             // A 16K+16K, B 8K+8K
#define R3_AHI 0
#define R3_ALO 16384
#define R3_BHI 32768
#define R3_BLO 40960

// K2 tiling: M=128, N=128, 512 threads
#define K2_BK 64
#define K2_STAGE 65536             // A 16K+16K, B 16K+16K
#define S_AHI 0
#define S_ALO 16384
#define S_BHI 32768
#define S_BLO 49152

// K1 tiling: N=64, 256 threads (R10 proven)
#define K1_STAGE 49152
#define T_AHI 0
#define T_ALO 16384
#define T_BHI 32768
#define T_BLO 40960

// -------- scratch (device globals; no allocation allowed) --------
__device__ float g_head_cat[N_OBJ * POOL];
__device__ float g_tail_cat[N_OBJ * POOL];
__device__ float g_part[R3_SPLITK * N_REL * NPAD];
__device__ __nv_bfloat16 g_A_hi[N_OBJ * 2 * HID];        // edge_rep hi
__device__ __nv_bfloat16 g_A_lo[N_OBJ * 2 * HID];
__device__ __nv_bfloat16 g_Bt_hi[POOL * 2 * HID];        // W_post_cat^T
__device__ __nv_bfloat16 g_Bt_lo[POOL * 2 * HID];
__device__ __nv_bfloat16 g_Wt_hi[NPAD * POOL];           // W_rel^T, rows>=51 zero
__device__ __nv_bfloat16 g_Wt_lo[NPAD * POOL];
__device__ __nv_bfloat16 g_Ec_hi[N_OBJ * HID];           // edge_ctx split
__device__ __nv_bfloat16 g_Ec_lo[N_OBJ * HID];
__device__ __nv_bfloat16 g_We_hi[(2 * HID) * HID];       // W_post_emb^T split
__device__ __nv_bfloat16 g_We_lo[(2 * HID) * HID];

// =====================================================================
// helpers
// =====================================================================
__device__ __forceinline__ uint32_t smem_u32(const void* p) {
    uint32_t a;
    asm("{ .reg .u64 t; cvta.to.shared.u64 t, %1; cvt.u32.u64 %0, t; }"
        : "=r"(a) : "l"(p));
    return a;
}
#define SWZ128(off) ((off) ^ (((off) >> 3) & 0x70))

__device__ __forceinline__ void cp16(uint32_t s, const void* g) {
    asm volatile("cp.async.cg.shared.global [%0], [%1], 16;" :: "r"(s), "l"(g));
}
#define CP_COMMIT() asm volatile("cp.async.commit_group;" ::: "memory")
#define CP_WAIT0()  asm volatile("cp.async.wait_group 0;" ::: "memory")
#define CP_WAIT1()  asm volatile("cp.async.wait_group 1;" ::: "memory")

__device__ __forceinline__ void ldsm_x4(uint32_t* r, uint32_t addr) {
    asm volatile("ldmatrix.sync.aligned.m8n8.x4.shared.b16 {%0,%1,%2,%3}, [%4];"
                 : "=r"(r[0]), "=r"(r[1]), "=r"(r[2]), "=r"(r[3]) : "r"(addr));
}

__device__ __forceinline__ void mma_bf16(float* d, const uint32_t* a, const uint32_t* b) {
    asm volatile(
        "mma.sync.aligned.m16n8k16.row.col.f32.bf16.bf16.f32 "
        "{%0,%1,%2,%3}, {%4,%5,%6,%7}, {%8,%9}, {%0,%1,%2,%3};"
        : "+f"(d[0]), "+f"(d[1]), "+f"(d[2]), "+f"(d[3])
        : "r"(a[0]), "r"(a[1]), "r"(a[2]), "r"(a[3]), "r"(b[0]), "r"(b[1]));
}

__device__ __forceinline__ uint32_t pack_hi(float a, float b) {
    __nv_bfloat162 h;
    h.x = __float2bfloat16(a);
    h.y = __float2bfloat16(b);
    return *(uint32_t*)&h;
}
__device__ __forceinline__ uint32_t pack_lo(float a, float b, uint32_t hw) {
    __nv_bfloat162 h = *(__nv_bfloat162*)&hw;
    __nv_bfloat162 l;
    l.x = __float2bfloat16(a - __bfloat162float(h.x));
    l.y = __float2bfloat16(b - __bfloat162float(h.y));
    return *(uint32_t*)&l;
}

// =====================================================================
// preprocessing
// =====================================================================
__global__ __launch_bounds__(256) void split_simple(
    const float* __restrict__ src, __nv_bfloat16* __restrict__ hi,
    __nv_bfloat16* __restrict__ lo, int n)
{
    int i = blockIdx.x * 256 + threadIdx.x;
    if (i >= n) return;
    float x = src[i];
    __nv_bfloat16 h = __float2bfloat16(x);
    hi[i] = h;
    lo[i] = __float2bfloat16(x - __bfloat162float(h));
}

__global__ __launch_bounds__(256) void transpose_split(
    const float* __restrict__ W, int R, int C,
    __nv_bfloat16* __restrict__ bhi, __nv_bfloat16* __restrict__ blo)
{
    __shared__ float t[32][33];
    const int kb = blockIdx.y * 32;
    const int nb = blockIdx.x * 32;
    const int tx = threadIdx.x & 31;
    const int ty = threadIdx.x >> 5;
    #pragma unroll
    for (int s = 0; s < 4; s++)
        t[ty + s * 8][tx] = W[(size_t)(kb + ty + s * 8) * C + nb + tx];
    __syncthreads();
    #pragma unroll
    for (int s = 0; s < 4; s++) {
        const int n = nb + ty + s * 8;
        const float x = t[tx][ty + s * 8];
        __nv_bfloat16 h = __float2bfloat16(x);
        const size_t o = (size_t)n * R + kb + tx;
        bhi[o] = h;
        blo[o] = __float2bfloat16(x - __bfloat162float(h));
    }
}

__global__ __launch_bounds__(256) void transpose_split_Wrel(
    const float* __restrict__ Wr,
    __nv_bfloat16* __restrict__ whi, __nv_bfloat16* __restrict__ wlo)
{
    __shared__ float t[32][33];
    const int kb = blockIdx.y * 32;
    const int nb = blockIdx.x * 32;
    const int tx = threadIdx.x & 31;
    const int ty = threadIdx.x >> 5;
    #pragma unroll
    for (int s = 0; s < 4; s++) {
        const int k = kb + ty + s * 8;
        const int n = nb + tx;
        t[ty + s * 8][tx] = (n < NUM_REL_CLS) ? Wr[(size_t)k * NUM_REL_CLS + n] : 0.0f;
    }
    __syncthreads();
    #pragma unroll
    for (int s = 0; s < 4; s++) {
        const int n = nb + ty + s * 8;
        const float x = t[tx][ty + s * 8];
        __nv_bfloat16 h = __float2bfloat16(x);
        const size_t o = (size_t)n * POOL + kb + tx;
        whi[o] = h;
        wlo[o] = __float2bfloat16(x - __bfloat162float(h));
    }
}

// =====================================================================
// K1 via HMMA (R10 proven, 256 threads, N=64)
// =====================================================================
__global__ __launch_bounds__(256) void k1_hmma(
    const __nv_bfloat16* __restrict__ Ahi, const __nv_bfloat16* __restrict__ Alo,
    const __nv_bfloat16* __restrict__ Bhi, const __nv_bfloat16* __restrict__ Blo,
    const float* __restrict__ bias,
    __nv_bfloat16* __restrict__ Ohi, __nv_bfloat16* __restrict__ Olo)
{
    extern __shared__ char smem[];
    const uint32_t sb = smem_u32(smem);
    const int tid = threadIdx.x;
    const int wid = tid >> 5;
    const int lane = tid & 31;
    const int bx = blockIdx.x;
    const int by = blockIdx.y;
    const int NCH = HID / K2_BK;

    const int m0 = (wid >> 1) * 32;
    const int n0 = (wid & 1) * 32;

    float acc[2][4][4];
    #pragma unroll
    for (int mf = 0; mf < 2; mf++)
        #pragma unroll
        for (int nf = 0; nf < 4; nf++)
            #pragma unroll
            for (int e = 0; e < 4; e++) acc[mf][nf][e] = 0.0f;

    const int aRowOff = (m0 + (lane & 15)) * 128 + ((lane & 16) ? 16 : 0);
    const int bRowOff = (n0 + (lane & 7) + ((lane & 16) ? 8 : 0)) * 128 + ((lane & 8) ? 16 : 0);

    auto STAGE = [&](int ch, int stg) {
        const int k0 = ch * K2_BK;
        const uint32_t base = sb + stg * K1_STAGE;
        #pragma unroll
        for (int it = 0; it < 4; it++) {
            const int g = tid + it * 256;
            const int row = g >> 3, grp = g & 7;
            const size_t src = (size_t)(by * 128 + row) * HID + k0 + grp * 8;
            const uint32_t off = SWZ128((uint32_t)(row * 128 + grp * 16));
            cp16(base + T_AHI + off, Ahi + src);
            cp16(base + T_ALO + off, Alo + src);
        }
        #pragma unroll
        for (int it = 0; it < 2; it++) {
            const int g = tid + it * 256;
            const int row = g >> 3, grp = g & 7;
            const size_t src = (size_t)(bx * 64 + row) * HID + k0 + grp * 8;
            const uint32_t off = SWZ128((uint32_t)(row * 128 + grp * 16));
            cp16(base + T_BHI + off, Bhi + src);
            cp16(base + T_BLO + off, Blo + src);
        }
        CP_COMMIT();
    };

    STAGE(0, 0);
    int buf = 0;
    for (int ch = 0; ch < NCH; ch++) {
        const bool nxt = (ch + 1) < NCH;
        if (nxt) STAGE(ch + 1, buf ^ 1);
        if (nxt) CP_WAIT1(); else CP_WAIT0();
        __syncthreads();

        const uint32_t base = sb + buf * K1_STAGE;
        #pragma unroll
        for (int kk = 0; kk < K2_BK; kk += 16) {
            uint32_t ahi[2][4], alo[2][4], bh[2][4], bl[2][4];
            #pragma unroll
            for (int mf = 0; mf < 2; mf++) {
                const uint32_t off = SWZ128((uint32_t)(aRowOff + mf * 16 * 128 + kk * 2));
                ldsm_x4(ahi[mf], base + T_AHI + off);
                ldsm_x4(alo[mf], base + T_ALO + off);
            }
            #pragma unroll
            for (int nf2 = 0; nf2 < 2; nf2++) {
                const uint32_t off = SWZ128((uint32_t)(bRowOff + nf2 * 16 * 128 + kk * 2));
                ldsm_x4(bh[nf2], base + T_BHI + off);
                ldsm_x4(bl[nf2], base + T_BLO + off);
            }
            #pragma unroll
            for (int mf = 0; mf < 2; mf++) {
                #pragma unroll
                for (int nf = 0; nf < 4; nf++) {
                    const uint32_t* bhp = &bh[nf >> 1][(nf & 1) * 2];
                    const uint32_t* blp = &bl[nf >> 1][(nf & 1) * 2];
                    mma_bf16(acc[mf][nf], ahi[mf], bhp);
                    mma_bf16(acc[mf][nf], ahi[mf], blp);
                    mma_bf16(acc[mf][nf], alo[mf], bhp);
                }
            }
        }
        __syncthreads();
        buf ^= 1;
    }

    const int gm = by * 128 + m0 + (lane >> 2);
    const int gn = bx * 64 + n0 + (lane & 3) * 2;
    #pragma unroll
    for (int mf = 0; mf < 2; mf++) {
        #pragma unroll
        for (int nf = 0; nf < 4; nf++) {
            const int col = gn + nf * 8;
            const float b0 = bias[col], b1 = bias[col + 1];
            const int r0 = gm + mf * 16;
            float v0x = acc[mf][nf][0] + b0, v0y = acc[mf][nf][1] + b1;
            float v1x = acc[mf][nf][2] + b0, v1y = acc[mf][nf][3] + b1;
            uint32_t h0 = pack_hi(v0x, v0y), l0 = pack_lo(v0x, v0y, h0);
            uint32_t h1 = pack_hi(v1x, v1y), l1 = pack_lo(v1x, v1y, h1);
            *(uint32_t*)&Ohi[(size_t)r0 * (2 * HID) + col] = h0;
            *(uint32_t*)&Olo[(size_t)r0 * (2 * HID) + col] = l0;
            *(uint32_t*)&Ohi[(size_t)(r0 + 8) * (2 * HID) + col] = h1;
            *(uint32_t*)&Olo[(size_t)(r0 + 8) * (2 * HID) + col] = l1;
        }
    }
}

// =====================================================================
// K2 via HMMA: M=128, N=128 tile, 512 threads (16 warps, 4m x 4n).
// A-tile traffic halves vs N=64. smem 2 x 64KB = 128KB dynamic.
// =====================================================================
__global__ __launch_bounds__(512) void k2_hmma(
    const __nv_bfloat16* __restrict__ Ahi, const __nv_bfloat16* __restrict__ Alo,
    const __nv_bfloat16* __restrict__ Bhi, const __nv_bfloat16* __restrict__ Blo,
    const float* __restrict__ bpc,
    float* __restrict__ hc, float* __restrict__ tcat)
{
    extern __shared__ char smem[];
    const uint32_t sb = smem_u32(smem);
    const int tid = threadIdx.x;
    const int wid = tid >> 5;
    const int lane = tid & 31;
    const int bx = blockIdx.x;
    const int by = blockIdx.y;
    const int z = blockIdx.z;
    const int koff = z * HID;
    const int NCH = HID / K2_BK;

    const int m0 = (wid >> 2) * 32;      // 4 m-warps: 0,32,64,96
    const int n0 = (wid & 3) * 32;       // 4 n-warps: 0,32,64,96

    float acc[2][4][4];
    #pragma unroll
    for (int mf = 0; mf < 2; mf++)
        #pragma unroll
        for (int nf = 0; nf < 4; nf++)
            #pragma unroll
            for (int e = 0; e < 4; e++) acc[mf][nf][e] = 0.0f;

    const int aRowOff = (m0 + (lane & 15)) * 128 + ((lane & 16) ? 16 : 0);
    const int bRowOff = (n0 + (lane & 7) + ((lane & 16) ? 8 : 0)) * 128 + ((lane & 8) ? 16 : 0);

    auto STAGE = [&](int ch, int stg) {
        const int k0 = koff + ch * K2_BK;
        const uint32_t base = sb + stg * K2_STAGE;
        #pragma unroll
        for (int it = 0; it < 2; it++) {
            const int g = tid + it * 512;
            const int row = g >> 3, grp = g & 7;
            const size_t srcA = (size_t)(by * 128 + row) * (2 * HID) + k0 + grp * 8;
            const size_t srcB = (size_t)(bx * 128 + row) * (2 * HID) + k0 + grp * 8;
            const uint32_t off = SWZ128((uint32_t)(row * 128 + grp * 16));
            cp16(base + S_AHI + off, Ahi + srcA);
            cp16(base + S_ALO + off, Alo + srcA);
            cp16(base + S_BHI + off, Bhi + srcB);
            cp16(base + S_BLO + off, Blo + srcB);
        }
        CP_COMMIT();
    };

    STAGE(0, 0);
    int buf = 0;
    for (int ch = 0; ch < NCH; ch++) {
        const bool nxt = (ch + 1) < NCH;
        if (nxt) STAGE(ch + 1, buf ^ 1);
        if (nxt) CP_WAIT1(); else CP_WAIT0();
        __syncthreads();

        const uint32_t base = sb + buf * K2_STAGE;
        #pragma unroll
        for (int kk = 0; kk < K2_BK; kk += 16) {
            uint32_t ahi[2][4], alo[2][4], bh[2][4], bl[2][4];
            #pragma unroll
            for (int mf = 0; mf < 2; mf++) {
                const uint32_t off = SWZ128((uint32_t)(aRowOff + mf * 16 * 128 + kk * 2));
                ldsm_x4(ahi[mf], base + S_AHI + off);
                ldsm_x4(alo[mf], base + S_ALO + off);
            }
            #pragma unroll
            for (int nf2 = 0; nf2 < 2; nf2++) {
                const uint32_t off = SWZ128((uint32_t)(bRowOff + nf2 * 16 * 128 + kk * 2));
                ldsm_x4(bh[nf2], base + S_BHI + off);
                ldsm_x4(bl[nf2], base + S_BLO + off);
            }
            #pragma unroll
            for (int mf = 0; mf < 2; mf++) {
                #pragma unroll
                for (int nf = 0; nf < 4; nf++) {
                    const uint32_t* bhp = &bh[nf >> 1][(nf & 1) * 2];
                    const uint32_t* blp = &bl[nf >> 1][(nf & 1) * 2];
                    mma_bf16(acc[mf][nf], ahi[mf], bhp);
                    mma_bf16(acc[mf][nf], ahi[mf], blp);
                    mma_bf16(acc[mf][nf], alo[mf], bhp);
                }
            }
        }
        __syncthreads();
        buf ^= 1;
    }

    const int gm = by * 128 + m0 + (lane >> 2);
    const int gn = bx * 128 + n0 + (lane & 3) * 2;
    float* Cb = (z == 0 ? hc : tcat);
    #pragma unroll
    for (int mf = 0; mf < 2; mf++) {
        #pragma unroll
        for (int nf = 0; nf < 4; nf++) {
            const int col = gn + nf * 8;
            float b0 = 0.0f, b1 = 0.0f;
            if (z == 0) { b0 = bpc[col]; b1 = bpc[col + 1]; }
            const int r0 = gm + mf * 16;
            float2 v0, v1;
            v0.x = acc[mf][nf][0] + b0;
            v0.y = acc[mf][nf][1] + b1;
            v1.x = acc[mf][nf][2] + b0;
            v1.y = acc[mf][nf][3] + b1;
            *(float2*)&Cb[(size_t)r0 * POOL + col] = v0;
            *(float2*)&Cb[(size_t)(r0 + 8) * POOL + col] = v1;
        }
    }
}

// =====================================================================
// K3 via HMMA: M=128, 512 threads (16 warps, 4m x 4n of 32x16),
// split-K=4, register prefetch (per-thread structure identical to R11).
// smem 2 x 48KB = 96KB dynamic.
// =====================================================================
__global__ __launch_bounds__(512) void k3_hmma(
    const float* __restrict__ U,
    const float* __restrict__ HC,
    const float* __restrict__ TC,
    const __nv_bfloat16* __restrict__ Whi,
    const __nv_bfloat16* __restrict__ Wlo,
    const int* __restrict__ pair_idx,
    float* __restrict__ part)
{
    extern __shared__ char smem[];
    const uint32_t sb = smem_u32(smem);
    const int tid = threadIdx.x;
    const int wid = tid >> 5;
    const int lane = tid & 31;
    const int rBase = blockIdx.x * R3_M;
    const int sp = blockIdx.y;
    const int kb = sp * R3_KS;

    const int m0 = (wid >> 2) * 32;      // 4 m-warps: 0,32,64,96
    const int n0 = (wid & 3) * 16;       // 4 n-warps: 0,16,32,48

    const int sRow = tid >> 2;           // 0..127
    const int sK = (tid & 3) * 16;
    const int grow = rBase + sRow;
    const int si = pair_idx[2 * grow];
    const int sj = pair_idx[2 * grow + 1];
    const float* hp = HC + (size_t)si * POOL + kb + sK;
    const float* tp = TC + (size_t)sj * POOL + kb + sK;
    const float* up = U  + (size_t)grow * POOL + kb + sK;
    const int sgrp = (tid & 3) * 2;

    float4 ru[4], rh[4], rt[4];

    auto PRELOAD = [&](int ch) {
        #pragma unroll
        for (int s = 0; s < 4; s++) {
            ru[s] = *(const float4*)(up + ch * R3_BK + s * 4);
            rh[s] = *(const float4*)(hp + ch * R3_BK + s * 4);
            rt[s] = *(const float4*)(tp + ch * R3_BK + s * 4);
        }
    };
    auto ASTORE = [&](int stg) {
        float mv[16];
        #pragma unroll
        for (int s = 0; s < 4; s++) {
            mv[s * 4 + 0] = (rh[s].x + rt[s].x) * ru[s].x;
            mv[s * 4 + 1] = (rh[s].y + rt[s].y) * ru[s].y;
            mv[s * 4 + 2] = (rh[s].z + rt[s].z) * ru[s].z;
            mv[s * 4 + 3] = (rh[s].w + rt[s].w) * ru[s].w;
        }
        #pragma unroll
        for (int g2 = 0; g2 < 2; g2++) {
            uint4 hw, lw;
            uint32_t* hp4 = (uint32_t*)&hw;
            uint32_t* lp4 = (uint32_t*)&lw;
            #pragma unroll
            for (int p = 0; p < 4; p++) {
                const float a = mv[g2 * 8 + p * 2];
                const float b = mv[g2 * 8 + p * 2 + 1];
                hp4[p] = pack_hi(a, b);
                lp4[p] = pack_lo(a, b, hp4[p]);
            }
            const uint32_t dst = SWZ128((uint32_t)(sRow * 128 + (sgrp + g2) * 16));
            *(uint4*)(smem + stg * R3_STAGE + R3_AHI + dst) = hw;
            *(uint4*)(smem + stg * R3_STAGE + R3_ALO + dst) = lw;
        }
    };
    auto BSTAGE = [&](int ch, int stg) {
        const uint32_t base = sb + stg * R3_STAGE;
        {
            const int g = tid;                 // 512 threads cover 64x8 groups
            const int row = g >> 3, grp = g & 7;
            const size_t src = (size_t)row * POOL + kb + ch * R3_BK + grp * 8;
            const uint32_t off = SWZ128((uint32_t)(row * 128 + grp * 16));
            cp16(base + R3_BHI + off, Whi + src);
            cp16(base + R3_BLO + off, Wlo + src);
        }
        CP_COMMIT();
    };

    float acc[2][2][4];
    #pragma unroll
    for (int mf = 0; mf < 2; mf++)
        #pragma unroll
        for (int nf = 0; nf < 2; nf++)
            #pragma unroll
            for (int e = 0; e < 4; e++) acc[mf][nf][e] = 0.0f;

    const int aRowOff = (m0 + (lane & 15)) * 128 + ((lane & 16) ? 16 : 0);
    const int bRowOff = (n0 + (lane & 7) + ((lane & 16) ? 8 : 0)) * 128 + ((lane & 8) ? 16 : 0);

    PRELOAD(0);
    ASTORE(0);
    BSTAGE(0, 0);
    BSTAGE(1, 1);

    int buf = 0;
    for (int ch = 0; ch < R3_NCH; ch++) {
        const bool nxt = (ch + 1) < R3_NCH;
        if (nxt) CP_WAIT1(); else CP_WAIT0();
        __syncthreads();

        if (nxt) PRELOAD(ch + 1);

        const uint32_t base = sb + buf * R3_STAGE;
        #pragma unroll
        for (int kk = 0; kk < R3_BK; kk += 16) {
            uint32_t ahi[2][4], alo[2][4], bh[4], bl[4];
            #pragma unroll
            for (int mf = 0; mf < 2; mf++) {
                const uint32_t off = SWZ128((uint32_t)(aRowOff + mf * 16 * 128 + kk * 2));
                ldsm_x4(ahi[mf], base + R3_AHI + off);
                ldsm_x4(alo[mf], base + R3_ALO + off);
            }
            {
                const uint32_t off = SWZ128((uint32_t)(bRowOff + kk * 2));
                ldsm_x4(bh, base + R3_BHI + off);
                ldsm_x4(bl, base + R3_BLO + off);
            }
            #pragma unroll
            for (int mf = 0; mf < 2; mf++) {
                #pragma unroll
                for (int nf = 0; nf < 2; nf++) {
                    const uint32_t* bhp = &bh[nf * 2];
                    const uint32_t* blp = &bl[nf * 2];
                    mma_bf16(acc[mf][nf], ahi[mf], bhp);
                    mma_bf16(acc[mf][nf], ahi[mf], blp);
                    mma_bf16(acc[mf][nf], alo[mf], bhp);
                }
            }
        }
        __syncthreads();

        if (nxt) {
            ASTORE(buf ^ 1);
            if (ch + 2 < R3_NCH) BSTAGE(ch + 2, buf);
        }
        buf ^= 1;
    }

    const int gm = rBase + m0 + (lane >> 2);
    const int gn = n0 + (lane & 3) * 2;
    float* pb = part + (size_t)sp * N_REL * NPAD;
    #pragma unroll
    for (int mf = 0; mf < 2; mf++) {
        #pragma unroll
        for (int nf = 0; nf < 2; nf++) {
            const int col = gn + nf * 8;
            const int r0 = gm + mf * 16;
            float2 v0, v1;
            v0.x = acc[mf][nf][0];
            v0.y = acc[mf][nf][1];
            v1.x = acc[mf][nf][2];
            v1.y = acc[mf][nf][3];
            *(float2*)&pb[(size_t)r0 * NPAD + col] = v0;
            *(float2*)&pb[(size_t)(r0 + 8) * NPAD + col] = v1;
        }
    }
}

// =====================================================================
// combine
// =====================================================================
__global__ __launch_bounds__(256) void combine_rel(
    const float* __restrict__ part,
    const float* __restrict__ br,
    const float* __restrict__ freq,
    const int* __restrict__ pair_idx,
    const int* __restrict__ obj_preds,
    float* __restrict__ out)
{
    const int r = blockIdx.x * 4 + (threadIdx.x >> 6);
    const int c = threadIdx.x & 63;
    if (c >= NUM_REL_CLS) return;

    const int bi = obj_preds[pair_idx[2 * r]] * NUM_OBJ_CLS
                 + obj_preds[pair_idx[2 * r + 1]];
    float s = 0.0f;
    #pragma unroll
    for (int sp = 0; sp < R3_SPLITK; sp++)
        s += part[((size_t)sp * N_REL + r) * NPAD + c];
    out[(size_t)r * NUM_REL_CLS + c] = s + br[c] + freq[(size_t)bi * NUM_REL_CLS + c];
}

// =====================================================================
// Launch
// =====================================================================
extern "C" void kernel_launch(void* const* d_in, const int* in_sizes, int n_in,
                              void* d_out, int out_size)
{
    const float* edge_ctx   = (const float*)d_in[0];
    const float* U          = (const float*)d_in[1];
    const float* W_post_emb = (const float*)d_in[2];
    const float* b_post_emb = (const float*)d_in[3];
    const float* W_post_cat = (const float*)d_in[4];
    const float* b_post_cat = (const float*)d_in[5];
    const float* W_rel      = (const float*)d_in[6];
    const float* b_rel      = (const float*)d_in[7];
    const float* freq       = (const float*)d_in[8];
    const int*   pair_idx   = (const int*)d_in[9];
    const int*   obj_preds  = (const int*)d_in[10];
    float* out = (float*)d_out;

    float *hc, *tc, *part;
    __nv_bfloat16 *ahi, *alo, *bhi, *blo, *whi, *wlo, *echi, *eclo, *wehi, *welo;
    cudaGetSymbolAddress((void**)&hc, g_head_cat);
    cudaGetSymbolAddress((void**)&tc, g_tail_cat);
    cudaGetSymbolAddress((void**)&part, g_part);
    cudaGetSymbolAddress((void**)&ahi, g_A_hi);
    cudaGetSymbolAddress((void**)&alo, g_A_lo);
    cudaGetSymbolAddress((void**)&bhi, g_Bt_hi);
    cudaGetSymbolAddress((void**)&blo, g_Bt_lo);
    cudaGetSymbolAddress((void**)&whi, g_Wt_hi);
    cudaGetSymbolAddress((void**)&wlo, g_Wt_lo);
    cudaGetSymbolAddress((void**)&echi, g_Ec_hi);
    cudaGetSymbolAddress((void**)&eclo, g_Ec_lo);
    cudaGetSymbolAddress((void**)&wehi, g_We_hi);
    cudaGetSymbolAddress((void**)&welo, g_We_lo);

    static bool attr_done = false;
    if (!attr_done) {
        cudaFuncSetAttribute(k1_hmma, cudaFuncAttributeMaxDynamicSharedMemorySize,
                             2 * K1_STAGE);
        cudaFuncSetAttribute(k2_hmma, cudaFuncAttributeMaxDynamicSharedMemorySize,
                             2 * K2_STAGE);
        cudaFuncSetAttribute(k3_hmma, cudaFuncAttributeMaxDynamicSharedMemorySize,
                             2 * R3_STAGE);
        attr_done = true;
    }

    // preprocessing
    split_simple<<<(N_OBJ * HID + 255) / 256, 256>>>(edge_ctx, echi, eclo, N_OBJ * HID);
    transpose_split<<<dim3((2 * HID) / 32, HID / 32), 256>>>(
        W_post_emb, HID, 2 * HID, wehi, welo);
    transpose_split_Wrel<<<dim3(NPAD / 32, POOL / 32), 256>>>(W_rel, whi, wlo);
    transpose_split<<<dim3(POOL / 32, (2 * HID) / 32), 256>>>(
        W_post_cat, 2 * HID, POOL, bhi, blo);

    // K1: edge_rep via HMMA, bf16 split output
    k1_hmma<<<dim3((2 * HID) / 64, N_OBJ / 128), 256, 2 * K1_STAGE>>>(
        echi, eclo, wehi, welo, b_post_emb, ahi, alo);

    // K2: head_cat / tail_cat via HMMA, N=128 tile, 512 threads
    k2_hmma<<<dim3(POOL / 128, N_OBJ / 128, 2), 512, 2 * K2_STAGE>>>(
        ahi, alo, bhi, blo, b_post_cat, hc, tc);

    // K3: fused gather+elementwise GEMM via HMMA, M=128, 512 threads
    k3_hmma<<<dim3(N_REL / R3_M, R3_SPLITK), 512, 2 * R3_STAGE>>>(
        U, hc, tc, whi, wlo, pair_idx, part);

    // K4: combine
    combine_rel<<<N_REL / 4, 256>>>(part, b_rel, freq, pair_idx, obj_preds, out);
}

// round 15
// speedup vs baseline: 1.2259x; 1.2259x over previous
#include <cuda_runtime.h>
#include <cuda_bf16.h>
#include <cstdint>

#define HID 512
#define POOL 4096
#define N_OBJ 1280
#define N_REL 16384
#define NUM_OBJ_CLS 151
#define NUM_REL_CLS 51
#define NPAD 64

// K3 tiling (R11 proven config)
#define R3_M 64
#define R3_BK 64
#define R3_SPLITK 2
#define R3_KS (POOL / R3_SPLITK)   // 2048
#define R3_NCH (R3_KS / R3_BK)     // 32
#define R3_STAGE 32768
#define R3_AHI 0
#define R3_ALO 8192
#define R3_BHI 16384
#define R3_BLO 24576

// K2/K1 hmma tiling (R11 proven config)
#define K2_BK 64
#define K2_STAGE 49152
#define S_AHI 0
#define S_ALO 16384
#define S_BHI 32768
#define S_BLO 40960

// -------- scratch (device globals; no allocation allowed) --------
__device__ float g_head_cat[N_OBJ * POOL];
__device__ float g_tail_cat[N_OBJ * POOL];
__device__ float g_part[R3_SPLITK * N_REL * NPAD];
__device__ __nv_bfloat16 g_A_hi[N_OBJ * 2 * HID];        // edge_rep hi
__device__ __nv_bfloat16 g_A_lo[N_OBJ * 2 * HID];
__device__ __nv_bfloat16 g_Bt_hi[POOL * 2 * HID];        // W_post_cat^T
__device__ __nv_bfloat16 g_Bt_lo[POOL * 2 * HID];
__device__ __nv_bfloat16 g_Wt_hi[NPAD * POOL];           // W_rel^T, rows>=51 zero
__device__ __nv_bfloat16 g_Wt_lo[NPAD * POOL];
__device__ __nv_bfloat16 g_Ec_hi[N_OBJ * HID];           // edge_ctx split
__device__ __nv_bfloat16 g_Ec_lo[N_OBJ * HID];
__device__ __nv_bfloat16 g_We_hi[(2 * HID) * HID];       // W_post_emb^T split
__device__ __nv_bfloat16 g_We_lo[(2 * HID) * HID];

// =====================================================================
// helpers
// =====================================================================
__device__ __forceinline__ uint32_t smem_u32(const void* p) {
    uint32_t a;
    asm("{ .reg .u64 t; cvta.to.shared.u64 t, %1; cvt.u32.u64 %0, t; }"
        : "=r"(a) : "l"(p));
    return a;
}
#define SWZ128(off) ((off) ^ (((off) >> 3) & 0x70))

__device__ __forceinline__ void cp16(uint32_t s, const void* g) {
    asm volatile("cp.async.cg.shared.global [%0], [%1], 16;" :: "r"(s), "l"(g));
}
#define CP_COMMIT() asm volatile("cp.async.commit_group;" ::: "memory")
#define CP_WAIT0()  asm volatile("cp.async.wait_group 0;" ::: "memory")
#define CP_WAIT1()  asm volatile("cp.async.wait_group 1;" ::: "memory")

__device__ __forceinline__ void ldsm_x4(uint32_t* r, uint32_t addr) {
    asm volatile("ldmatrix.sync.aligned.m8n8.x4.shared.b16 {%0,%1,%2,%3}, [%4];"
                 : "=r"(r[0]), "=r"(r[1]), "=r"(r[2]), "=r"(r[3]) : "r"(addr));
}

__device__ __forceinline__ void mma_bf16(float* d, const uint32_t* a, const uint32_t* b) {
    asm volatile(
        "mma.sync.aligned.m16n8k16.row.col.f32.bf16.bf16.f32 "
        "{%0,%1,%2,%3}, {%4,%5,%6,%7}, {%8,%9}, {%0,%1,%2,%3};"
        : "+f"(d[0]), "+f"(d[1]), "+f"(d[2]), "+f"(d[3])
        : "r"(a[0]), "r"(a[1]), "r"(a[2]), "r"(a[3]), "r"(b[0]), "r"(b[1]));
}

__device__ __forceinline__ uint32_t pack_hi(float a, float b) {
    __nv_bfloat162 h;
    h.x = __float2bfloat16(a);
    h.y = __float2bfloat16(b);
    return *(uint32_t*)&h;
}
__device__ __forceinline__ uint32_t pack_lo(float a, float b, uint32_t hw) {
    __nv_bfloat162 h = *(__nv_bfloat162*)&hw;
    __nv_bfloat162 l;
    l.x = __float2bfloat16(a - __bfloat162float(h.x));
    l.y = __float2bfloat16(b - __bfloat162float(h.y));
    return *(uint32_t*)&l;
}

// =====================================================================
// preprocessing
// =====================================================================
__global__ __launch_bounds__(256) void split_simple(
    const float* __restrict__ src, __nv_bfloat16* __restrict__ hi,
    __nv_bfloat16* __restrict__ lo, int n)
{
    int i = blockIdx.x * 256 + threadIdx.x;
    if (i >= n) return;
    float x = src[i];
    __nv_bfloat16 h = __float2bfloat16(x);
    hi[i] = h;
    lo[i] = __float2bfloat16(x - __bfloat162float(h));
}

__global__ __launch_bounds__(256) void transpose_split(
    const float* __restrict__ W, int R, int C,
    __nv_bfloat16* __restrict__ bhi, __nv_bfloat16* __restrict__ blo)
{
    __shared__ float t[32][33];
    const int kb = blockIdx.y * 32;
    const int nb = blockIdx.x * 32;
    const int tx = threadIdx.x & 31;
    const int ty = threadIdx.x >> 5;
    #pragma unroll
    for (int s = 0; s < 4; s++)
        t[ty + s * 8][tx] = W[(size_t)(kb + ty + s * 8) * C + nb + tx];
    __syncthreads();
    #pragma unroll
    for (int s = 0; s < 4; s++) {
        const int n = nb + ty + s * 8;
        const float x = t[tx][ty + s * 8];
        __nv_bfloat16 h = __float2bfloat16(x);
        const size_t o = (size_t)n * R + kb + tx;
        bhi[o] = h;
        blo[o] = __float2bfloat16(x - __bfloat162float(h));
    }
}

__global__ __launch_bounds__(256) void transpose_split_Wrel(
    const float* __restrict__ Wr,
    __nv_bfloat16* __restrict__ whi, __nv_bfloat16* __restrict__ wlo)
{
    __shared__ float t[32][33];
    const int kb = blockIdx.y * 32;
    const int nb = blockIdx.x * 32;
    const int tx = threadIdx.x & 31;
    const int ty = threadIdx.x >> 5;
    #pragma unroll
    for (int s = 0; s < 4; s++) {
        const int k = kb + ty + s * 8;
        const int n = nb + tx;
        t[ty + s * 8][tx] = (n < NUM_REL_CLS) ? Wr[(size_t)k * NUM_REL_CLS + n] : 0.0f;
    }
    __syncthreads();
    #pragma unroll
    for (int s = 0; s < 4; s++) {
        const int n = nb + ty + s * 8;
        const float x = t[tx][ty + s * 8];
        __nv_bfloat16 h = __float2bfloat16(x);
        const size_t o = (size_t)n * POOL + kb + tx;
        whi[o] = h;
        wlo[o] = __float2bfloat16(x - __bfloat162float(h));
    }
}

// =====================================================================
// K1 via HMMA (R10/R11 proven)
// =====================================================================
__global__ __launch_bounds__(256) void k1_hmma(
    const __nv_bfloat16* __restrict__ Ahi, const __nv_bfloat16* __restrict__ Alo,
    const __nv_bfloat16* __restrict__ Bhi, const __nv_bfloat16* __restrict__ Blo,
    const float* __restrict__ bias,
    __nv_bfloat16* __restrict__ Ohi, __nv_bfloat16* __restrict__ Olo)
{
    extern __shared__ char smem[];
    const uint32_t sb = smem_u32(smem);
    const int tid = threadIdx.x;
    const int wid = tid >> 5;
    const int lane = tid & 31;
    const int bx = blockIdx.x;
    const int by = blockIdx.y;
    const int NCH = HID / K2_BK;

    const int m0 = (wid >> 1) * 32;
    const int n0 = (wid & 1) * 32;

    float acc[2][4][4];
    #pragma unroll
    for (int mf = 0; mf < 2; mf++)
        #pragma unroll
        for (int nf = 0; nf < 4; nf++)
            #pragma unroll
            for (int e = 0; e < 4; e++) acc[mf][nf][e] = 0.0f;

    const int aRowOff = (m0 + (lane & 15)) * 128 + ((lane & 16) ? 16 : 0);
    const int bRowOff = (n0 + (lane & 7) + ((lane & 16) ? 8 : 0)) * 128 + ((lane & 8) ? 16 : 0);

    auto STAGE = [&](int ch, int stg) {
        const int k0 = ch * K2_BK;
        const uint32_t base = sb + stg * K2_STAGE;
        #pragma unroll
        for (int it = 0; it < 4; it++) {
            const int g = tid + it * 256;
            const int row = g >> 3, grp = g & 7;
            const size_t src = (size_t)(by * 128 + row) * HID + k0 + grp * 8;
            const uint32_t off = SWZ128((uint32_t)(row * 128 + grp * 16));
            cp16(base + S_AHI + off, Ahi + src);
            cp16(base + S_ALO + off, Alo + src);
        }
        #pragma unroll
        for (int it = 0; it < 2; it++) {
            const int g = tid + it * 256;
            const int row = g >> 3, grp = g & 7;
            const size_t src = (size_t)(bx * 64 + row) * HID + k0 + grp * 8;
            const uint32_t off = SWZ128((uint32_t)(row * 128 + grp * 16));
            cp16(base + S_BHI + off, Bhi + src);
            cp16(base + S_BLO + off, Blo + src);
        }
        CP_COMMIT();
    };

    STAGE(0, 0);
    int buf = 0;
    for (int ch = 0; ch < NCH; ch++) {
        const bool nxt = (ch + 1) < NCH;
        if (nxt) STAGE(ch + 1, buf ^ 1);
        if (nxt) CP_WAIT1(); else CP_WAIT0();
        __syncthreads();

        const uint32_t base = sb + buf * K2_STAGE;
        #pragma unroll
        for (int kk = 0; kk < K2_BK; kk += 16) {
            uint32_t ahi[2][4], alo[2][4], bh[2][4], bl[2][4];
            #pragma unroll
            for (int mf = 0; mf < 2; mf++) {
                const uint32_t off = SWZ128((uint32_t)(aRowOff + mf * 16 * 128 + kk * 2));
                ldsm_x4(ahi[mf], base + S_AHI + off);
                ldsm_x4(alo[mf], base + S_ALO + off);
            }
            #pragma unroll
            for (int nf2 = 0; nf2 < 2; nf2++) {
                const uint32_t off = SWZ128((uint32_t)(bRowOff + nf2 * 16 * 128 + kk * 2));
                ldsm_x4(bh[nf2], base + S_BHI + off);
                ldsm_x4(bl[nf2], base + S_BLO + off);
            }
            #pragma unroll
            for (int mf = 0; mf < 2; mf++) {
                #pragma unroll
                for (int nf = 0; nf < 4; nf++) {
                    const uint32_t* bhp = &bh[nf >> 1][(nf & 1) * 2];
                    const uint32_t* blp = &bl[nf >> 1][(nf & 1) * 2];
                    mma_bf16(acc[mf][nf], ahi[mf], bhp);
                    mma_bf16(acc[mf][nf], ahi[mf], blp);
                    mma_bf16(acc[mf][nf], alo[mf], bhp);
                }
            }
        }
        __syncthreads();
        buf ^= 1;
    }

    const int gm = by * 128 + m0 + (lane >> 2);
    const int gn = bx * 64 + n0 + (lane & 3) * 2;
    #pragma unroll
    for (int mf = 0; mf < 2; mf++) {
        #pragma unroll
        for (int nf = 0; nf < 4; nf++) {
            const int col = gn + nf * 8;
            const float b0 = bias[col], b1 = bias[col + 1];
            const int r0 = gm + mf * 16;
            float v0x = acc[mf][nf][0] + b0, v0y = acc[mf][nf][1] + b1;
            float v1x = acc[mf][nf][2] + b0, v1y = acc[mf][nf][3] + b1;
            uint32_t h0 = pack_hi(v0x, v0y), l0 = pack_lo(v0x, v0y, h0);
            uint32_t h1 = pack_hi(v1x, v1y), l1 = pack_lo(v1x, v1y, h1);
            *(uint32_t*)&Ohi[(size_t)r0 * (2 * HID) + col] = h0;
            *(uint32_t*)&Olo[(size_t)r0 * (2 * HID) + col] = l0;
            *(uint32_t*)&Ohi[(size_t)(r0 + 8) * (2 * HID) + col] = h1;
            *(uint32_t*)&Olo[(size_t)(r0 + 8) * (2 * HID) + col] = l1;
        }
    }
}

// =====================================================================
// K2 via HMMA (R11 proven body; nBase selects the POOL column half)
// =====================================================================
__global__ __launch_bounds__(256) void k2_hmma(
    const __nv_bfloat16* __restrict__ Ahi, const __nv_bfloat16* __restrict__ Alo,
    const __nv_bfloat16* __restrict__ Bhi, const __nv_bfloat16* __restrict__ Blo,
    const float* __restrict__ bpc,
    float* __restrict__ hc, float* __restrict__ tcat, int nBase)
{
    extern __shared__ char smem[];
    const uint32_t sb = smem_u32(smem);
    const int tid = threadIdx.x;
    const int wid = tid >> 5;
    const int lane = tid & 31;
    const int bx = blockIdx.x + nBase;   // 64-col tile index within POOL
    const int by = blockIdx.y;
    const int z = blockIdx.z;
    const int koff = z * HID;
    const int NCH = HID / K2_BK;

    const int m0 = (wid >> 1) * 32;
    const int n0 = (wid & 1) * 32;

    float acc[2][4][4];
    #pragma unroll
    for (int mf = 0; mf < 2; mf++)
        #pragma unroll
        for (int nf = 0; nf < 4; nf++)
            #pragma unroll
            for (int e = 0; e < 4; e++) acc[mf][nf][e] = 0.0f;

    const int aRowOff = (m0 + (lane & 15)) * 128 + ((lane & 16) ? 16 : 0);
    const int bRowOff = (n0 + (lane & 7) + ((lane & 16) ? 8 : 0)) * 128 + ((lane & 8) ? 16 : 0);

    auto STAGE = [&](int ch, int stg) {
        const int k0 = koff + ch * K2_BK;
        const uint32_t base = sb + stg * K2_STAGE;
        #pragma unroll
        for (int it = 0; it < 4; it++) {
            const int g = tid + it * 256;
            const int row = g >> 3, grp = g & 7;
            const size_t src = (size_t)(by * 128 + row) * (2 * HID) + k0 + grp * 8;
            const uint32_t off = SWZ128((uint32_t)(row * 128 + grp * 16));
            cp16(base + S_AHI + off, Ahi + src);
            cp16(base + S_ALO + off, Alo + src);
        }
        #pragma unroll
        for (int it = 0; it < 2; it++) {
            const int g = tid + it * 256;
            const int row = g >> 3, grp = g & 7;
            const size_t src = (size_t)(bx * 64 + row) * (2 * HID) + k0 + grp * 8;
            const uint32_t off = SWZ128((uint32_t)(row * 128 + grp * 16));
            cp16(base + S_BHI + off, Bhi + src);
            cp16(base + S_BLO + off, Blo + src);
        }
        CP_COMMIT();
    };

    STAGE(0, 0);
    int buf = 0;
    for (int ch = 0; ch < NCH; ch++) {
        const bool nxt = (ch + 1) < NCH;
        if (nxt) STAGE(ch + 1, buf ^ 1);
        if (nxt) CP_WAIT1(); else CP_WAIT0();
        __syncthreads();

        const uint32_t base = sb + buf * K2_STAGE;
        #pragma unroll
        for (int kk = 0; kk < K2_BK; kk += 16) {
            uint32_t ahi[2][4], alo[2][4], bh[2][4], bl[2][4];
            #pragma unroll
            for (int mf = 0; mf < 2; mf++) {
                const uint32_t off = SWZ128((uint32_t)(aRowOff + mf * 16 * 128 + kk * 2));
                ldsm_x4(ahi[mf], base + S_AHI + off);
                ldsm_x4(alo[mf], base + S_ALO + off);
            }
            #pragma unroll
            for (int nf2 = 0; nf2 < 2; nf2++) {
                const uint32_t off = SWZ128((uint32_t)(bRowOff + nf2 * 16 * 128 + kk * 2));
                ldsm_x4(bh[nf2], base + S_BHI + off);
                ldsm_x4(bl[nf2], base + S_BLO + off);
            }
            #pragma unroll
            for (int mf = 0; mf < 2; mf++) {
                #pragma unroll
                for (int nf = 0; nf < 4; nf++) {
                    const uint32_t* bhp = &bh[nf >> 1][(nf & 1) * 2];
                    const uint32_t* blp = &bl[nf >> 1][(nf & 1) * 2];
                    mma_bf16(acc[mf][nf], ahi[mf], bhp);
                    mma_bf16(acc[mf][nf], ahi[mf], blp);
                    mma_bf16(acc[mf][nf], alo[mf], bhp);
                }
            }
        }
        __syncthreads();
        buf ^= 1;
    }

    const int gm = by * 128 + m0 + (lane >> 2);
    const int gn = bx * 64 + n0 + (lane & 3) * 2;
    float* Cb = (z == 0 ? hc : tcat);
    #pragma unroll
    for (int mf = 0; mf < 2; mf++) {
        #pragma unroll
        for (int nf = 0; nf < 4; nf++) {
            const int col = gn + nf * 8;
            float b0 = 0.0f, b1 = 0.0f;
            if (z == 0) { b0 = bpc[col]; b1 = bpc[col + 1]; }
            const int r0 = gm + mf * 16;
            float2 v0, v1;
            v0.x = acc[mf][nf][0] + b0;
            v0.y = acc[mf][nf][1] + b1;
            v1.x = acc[mf][nf][2] + b0;
            v1.y = acc[mf][nf][3] + b1;
            *(float2*)&Cb[(size_t)r0 * POOL + col] = v0;
            *(float2*)&Cb[(size_t)(r0 + 8) * POOL + col] = v1;
        }
    }
}

// =====================================================================
// K3 via HMMA (R11 proven body; sp passed as an argument)
// =====================================================================
__global__ __launch_bounds__(256, 2) void k3_hmma(
    const float* __restrict__ U,
    const float* __restrict__ HC,
    const float* __restrict__ TC,
    const __nv_bfloat16* __restrict__ Whi,
    const __nv_bfloat16* __restrict__ Wlo,
    const int* __restrict__ pair_idx,
    float* __restrict__ part, int sp)
{
    extern __shared__ char smem[];
    const uint32_t sb = smem_u32(smem);
    const int tid = threadIdx.x;
    const int wid = tid >> 5;
    const int lane = tid & 31;
    const int rBase = blockIdx.x * R3_M;
    const int kb = sp * R3_KS;

    const int m0 = (wid >> 2) * 32;
    const int n0 = (wid & 3) * 16;

    const int sRow = tid >> 2;
    const int sK = (tid & 3) * 16;
    const int grow = rBase + sRow;
    const int si = pair_idx[2 * grow];
    const int sj = pair_idx[2 * grow + 1];
    const float* hp = HC + (size_t)si * POOL + kb + sK;
    const float* tp = TC + (size_t)sj * POOL + kb + sK;
    const float* up = U  + (size_t)grow * POOL + kb + sK;
    const int sgrp = (tid & 3) * 2;

    float4 ru[4], rh[4], rt[4];

    auto PRELOAD = [&](int ch) {
        #pragma unroll
        for (int s = 0; s < 4; s++) {
            ru[s] = *(const float4*)(up + ch * R3_BK + s * 4);
            rh[s] = *(const float4*)(hp + ch * R3_BK + s * 4);
            rt[s] = *(const float4*)(tp + ch * R3_BK + s * 4);
        }
    };
    auto ASTORE = [&](int stg) {
        float mv[16];
        #pragma unroll
        for (int s = 0; s < 4; s++) {
            mv[s * 4 + 0] = (rh[s].x + rt[s].x) * ru[s].x;
            mv[s * 4 + 1] = (rh[s].y + rt[s].y) * ru[s].y;
            mv[s * 4 + 2] = (rh[s].z + rt[s].z) * ru[s].z;
            mv[s * 4 + 3] = (rh[s].w + rt[s].w) * ru[s].w;
        }
        #pragma unroll
        for (int g2 = 0; g2 < 2; g2++) {
            uint4 hw, lw;
            uint32_t* hp4 = (uint32_t*)&hw;
            uint32_t* lp4 = (uint32_t*)&lw;
            #pragma unroll
            for (int p = 0; p < 4; p++) {
                const float a = mv[g2 * 8 + p * 2];
                const float b = mv[g2 * 8 + p * 2 + 1];
                hp4[p] = pack_hi(a, b);
                lp4[p] = pack_lo(a, b, hp4[p]);
            }
            const uint32_t dst = SWZ128((uint32_t)(sRow * 128 + (sgrp + g2) * 16));
            *(uint4*)(smem + stg * R3_STAGE + R3_AHI + dst) = hw;
            *(uint4*)(smem + stg * R3_STAGE + R3_ALO + dst) = lw;
        }
    };
    auto BSTAGE = [&](int ch, int stg) {
        const uint32_t base = sb + stg * R3_STAGE;
        #pragma unroll
        for (int it = 0; it < 2; it++) {
            const int g = tid + it * 256;
            const int row = g >> 3, grp = g & 7;
            const size_t src = (size_t)row * POOL + kb + ch * R3_BK + grp * 8;
            const uint32_t off = SWZ128((uint32_t)(row * 128 + grp * 16));
            cp16(base + R3_BHI + off, Whi + src);
            cp16(base + R3_BLO + off, Wlo + src);
        }
        CP_COMMIT();
    };

    float acc[2][2][4];
    #pragma unroll
    for (int mf = 0; mf < 2; mf++)
        #pragma unroll
        for (int nf = 0; nf < 2; nf++)
            #pragma unroll
            for (int e = 0; e < 4; e++) acc[mf][nf][e] = 0.0f;

    const int aRowOff = (m0 + (lane & 15)) * 128 + ((lane & 16) ? 16 : 0);
    const int bRowOff = (n0 + (lane & 7) + ((lane & 16) ? 8 : 0)) * 128 + ((lane & 8) ? 16 : 0);

    PRELOAD(0);
    ASTORE(0);
    BSTAGE(0, 0);
    BSTAGE(1, 1);

    int buf = 0;
    for (int ch = 0; ch < R3_NCH; ch++) {
        const bool nxt = (ch + 1) < R3_NCH;
        if (nxt) CP_WAIT1(); else CP_WAIT0();
        __syncthreads();

        if (nxt) PRELOAD(ch + 1);

        const uint32_t base = sb + buf * R3_STAGE;
        #pragma unroll
        for (int kk = 0; kk < R3_BK; kk += 16) {
            uint32_t ahi[2][4], alo[2][4], bh[4], bl[4];
            #pragma unroll
            for (int mf = 0; mf < 2; mf++) {
                const uint32_t off = SWZ128((uint32_t)(aRowOff + mf * 16 * 128 + kk * 2));
                ldsm_x4(ahi[mf], base + R3_AHI + off);
                ldsm_x4(alo[mf], base + R3_ALO + off);
            }
            {
                const uint32_t off = SWZ128((uint32_t)(bRowOff + kk * 2));
                ldsm_x4(bh, base + R3_BHI + off);
                ldsm_x4(bl, base + R3_BLO + off);
            }
            #pragma unroll
            for (int mf = 0; mf < 2; mf++) {
                #pragma unroll
                for (int nf = 0; nf < 2; nf++) {
                    const uint32_t* bhp = &bh[nf * 2];
                    const uint32_t* blp = &bl[nf * 2];
                    mma_bf16(acc[mf][nf], ahi[mf], bhp);
                    mma_bf16(acc[mf][nf], ahi[mf], blp);
                    mma_bf16(acc[mf][nf], alo[mf], bhp);
                }
            }
        }
        __syncthreads();

        if (nxt) {
            ASTORE(buf ^ 1);
            if (ch + 2 < R3_NCH) BSTAGE(ch + 2, buf);
        }
        buf ^= 1;
    }

    const int gm = rBase + m0 + (lane >> 2);
    const int gn = n0 + (lane & 3) * 2;
    float* pb = part + (size_t)sp * N_REL * NPAD;
    #pragma unroll
    for (int mf = 0; mf < 2; mf++) {
        #pragma unroll
        for (int nf = 0; nf < 2; nf++) {
            const int col = gn + nf * 8;
            const int r0 = gm + mf * 16;
            float2 v0, v1;
            v0.x = acc[mf][nf][0];
            v0.y = acc[mf][nf][1];
            v1.x = acc[mf][nf][2];
            v1.y = acc[mf][nf][3];
            *(float2*)&pb[(size_t)r0 * NPAD + col] = v0;
            *(float2*)&pb[(size_t)(r0 + 8) * NPAD + col] = v1;
        }
    }
}

// =====================================================================
// combine
// =====================================================================
__global__ __launch_bounds__(256) void combine_rel(
    const float* __restrict__ part,
    const float* __restrict__ br,
    const float* __restrict__ freq,
    const int* __restrict__ pair_idx,
    const int* __restrict__ obj_preds,
    float* __restrict__ out)
{
    const int r = blockIdx.x * 4 + (threadIdx.x >> 6);
    const int c = threadIdx.x & 63;
    if (c >= NUM_REL_CLS) return;

    const int bi = obj_preds[pair_idx[2 * r]] * NUM_OBJ_CLS
                 + obj_preds[pair_idx[2 * r + 1]];
    float s = 0.0f;
    #pragma unroll
    for (int sp = 0; sp < R3_SPLITK; sp++)
        s += part[((size_t)sp * N_REL + r) * NPAD + c];
    out[(size_t)r * NUM_REL_CLS + c] = s + br[c] + freq[(size_t)bi * NUM_REL_CLS + c];
}

// =====================================================================
// Launch: stream-forked pipeline.
//   s0: split_simple -> transpose_We -> K1 -> [wait eB] -> K2_low -> K2_high
//   s2: transpose_Wrel -> transpose_B (eB) -> [wait eL] K3(sp0)
//       -> [wait eH] K3(sp1) (e3)
//   s0: [wait e3] combine
// =====================================================================
extern "C" void kernel_launch(void* const* d_in, const int* in_sizes, int n_in,
                              void* d_out, int out_size)
{
    const float* edge_ctx   = (const float*)d_in[0];
    const float* U          = (const float*)d_in[1];
    const float* W_post_emb = (const float*)d_in[2];
    const float* b_post_emb = (const float*)d_in[3];
    const float* W_post_cat = (const float*)d_in[4];
    const float* b_post_cat = (const float*)d_in[5];
    const float* W_rel      = (const float*)d_in[6];
    const float* b_rel      = (const float*)d_in[7];
    const float* freq       = (const float*)d_in[8];
    const int*   pair_idx   = (const int*)d_in[9];
    const int*   obj_preds  = (const int*)d_in[10];
    float* out = (float*)d_out;

    float *hc, *tc, *part;
    __nv_bfloat16 *ahi, *alo, *bhi, *blo, *whi, *wlo, *echi, *eclo, *wehi, *welo;
    cudaGetSymbolAddress((void**)&hc, g_head_cat);
    cudaGetSymbolAddress((void**)&tc, g_tail_cat);
    cudaGetSymbolAddress((void**)&part, g_part);
    cudaGetSymbolAddress((void**)&ahi, g_A_hi);
    cudaGetSymbolAddress((void**)&alo, g_A_lo);
    cudaGetSymbolAddress((void**)&bhi, g_Bt_hi);
    cudaGetSymbolAddress((void**)&blo, g_Bt_lo);
    cudaGetSymbolAddress((void**)&whi, g_Wt_hi);
    cudaGetSymbolAddress((void**)&wlo, g_Wt_lo);
    cudaGetSymbolAddress((void**)&echi, g_Ec_hi);
    cudaGetSymbolAddress((void**)&eclo, g_Ec_lo);
    cudaGetSymbolAddress((void**)&wehi, g_We_hi);
    cudaGetSymbolAddress((void**)&welo, g_We_lo);

    static bool init_done = false;
    static cudaStream_t s2;
    static cudaEvent_t ev0, eB, eL, eH, e3;
    if (!init_done) {
        cudaFuncSetAttribute(k1_hmma, cudaFuncAttributeMaxDynamicSharedMemorySize,
                             2 * K2_STAGE);
        cudaFuncSetAttribute(k2_hmma, cudaFuncAttributeMaxDynamicSharedMemorySize,
                             2 * K2_STAGE);
        cudaFuncSetAttribute(k3_hmma, cudaFuncAttributeMaxDynamicSharedMemorySize,
                             2 * R3_STAGE);
        cudaStreamCreateWithFlags(&s2, cudaStreamNonBlocking);
        cudaEventCreateWithFlags(&ev0, cudaEventDisableTiming);
        cudaEventCreateWithFlags(&eB, cudaEventDisableTiming);
        cudaEventCreateWithFlags(&eL, cudaEventDisableTiming);
        cudaEventCreateWithFlags(&eH, cudaEventDisableTiming);
        cudaEventCreateWithFlags(&e3, cudaEventDisableTiming);
        init_done = true;
    }

    // fork side stream from the (captured) origin stream
    cudaEventRecord(ev0, 0);
    cudaStreamWaitEvent(s2, ev0, 0);

    // s2: weight prep independent of K1
    transpose_split_Wrel<<<dim3(NPAD / 32, POOL / 32), 256, 0, s2>>>(W_rel, whi, wlo);
    transpose_split<<<dim3(POOL / 32, (2 * HID) / 32), 256, 0, s2>>>(
        W_post_cat, 2 * HID, POOL, bhi, blo);
    cudaEventRecord(eB, s2);

    // s0: edge_ctx/W_post_emb prep and K1
    split_simple<<<(N_OBJ * HID + 255) / 256, 256>>>(edge_ctx, echi, eclo, N_OBJ * HID);
    transpose_split<<<dim3((2 * HID) / 32, HID / 32), 256>>>(
        W_post_emb, HID, 2 * HID, wehi, welo);
    k1_hmma<<<dim3((2 * HID) / 64, N_OBJ / 128), 256, 2 * K2_STAGE>>>(
        echi, eclo, wehi, welo, b_post_emb, ahi, alo);

    // s0: K2 low half (cols 0..2047, 32 x-blocks), then high half
    cudaStreamWaitEvent(0, eB, 0);
    k2_hmma<<<dim3(32, N_OBJ / 128, 2), 256, 2 * K2_STAGE>>>(
        ahi, alo, bhi, blo, b_post_cat, hc, tc, 0);
    cudaEventRecord(eL, 0);
    k2_hmma<<<dim3(32, N_OBJ / 128, 2), 256, 2 * K2_STAGE>>>(
        ahi, alo, bhi, blo, b_post_cat, hc, tc, 32);
    cudaEventRecord(eH, 0);

    // s2: K3 sp0 (k 0..2047) overlaps K2 high half
    cudaStreamWaitEvent(s2, eL, 0);
    k3_hmma<<<dim3(N_REL / R3_M), 256, 2 * R3_STAGE, s2>>>(
        U, hc, tc, whi, wlo, pair_idx, part, 0);
    cudaStreamWaitEvent(s2, eH, 0);
    k3_hmma<<<dim3(N_REL / R3_M), 256, 2 * R3_STAGE, s2>>>(
        U, hc, tc, whi, wlo, pair_idx, part, 1);
    cudaEventRecord(e3, s2);

    // s0: join and combine
    cudaStreamWaitEvent(0, e3, 0);
    combine_rel<<<N_REL / 4, 256>>>(part, b_rel, freq, pair_idx, obj_preds, out);
}

// round 16
// speedup vs baseline: 1.2892x; 1.0517x over previous
#include <cuda_runtime.h>
#include <cuda_bf16.h>
#include <cstdint>

#define HID 512
#define POOL 4096
#define N_OBJ 1280
#define N_REL 16384
#define NUM_OBJ_CLS 151
#define NUM_REL_CLS 51
#define NPAD 64

// K3 tiling (R11 proven config)
#define R3_M 64
#define R3_BK 64
#define R3_SPLITK 2
#define R3_KS (POOL / R3_SPLITK)   // 2048
#define R3_NCH (R3_KS / R3_BK)     // 32
#define R3_STAGE 32768
#define R3_AHI 0
#define R3_ALO 8192
#define R3_BHI 16384
#define R3_BLO 24576

// K2/K1 hmma tiling (R11 proven config)
#define K2_BK 64
#define K2_STAGE 49152
#define S_AHI 0
#define S_ALO 16384
#define S_BHI 32768
#define S_BLO 40960

// -------- scratch (device globals; no allocation allowed) --------
__device__ float g_head_cat[N_OBJ * POOL];
__device__ float g_tail_cat[N_OBJ * POOL];
__device__ float g_part[R3_SPLITK * N_REL * NPAD];
__device__ __nv_bfloat16 g_A_hi[N_OBJ * 2 * HID];        // edge_rep hi
__device__ __nv_bfloat16 g_A_lo[N_OBJ * 2 * HID];
__device__ __nv_bfloat16 g_Bt_hi[POOL * 2 * HID];        // W_post_cat^T
__device__ __nv_bfloat16 g_Bt_lo[POOL * 2 * HID];
__device__ __nv_bfloat16 g_Wt_hi[NPAD * POOL];           // W_rel^T, rows>=51 zero
__device__ __nv_bfloat16 g_Wt_lo[NPAD * POOL];
__device__ __nv_bfloat16 g_Ec_hi[N_OBJ * HID];           // edge_ctx split
__device__ __nv_bfloat16 g_Ec_lo[N_OBJ * HID];
__device__ __nv_bfloat16 g_We_hi[(2 * HID) * HID];       // W_post_emb^T split
__device__ __nv_bfloat16 g_We_lo[(2 * HID) * HID];
__device__ int g_hist[2 * N_OBJ];                         // head hist | tail hist
__device__ int g_offs[2 * N_OBJ];                         // scanned offsets
__device__ int g_perm[2 * N_REL];                         // head-sorted | tail-sorted

// =====================================================================
// helpers
// =====================================================================
__device__ __forceinline__ uint32_t smem_u32(const void* p) {
    uint32_t a;
    asm("{ .reg .u64 t; cvta.to.shared.u64 t, %1; cvt.u32.u64 %0, t; }"
        : "=r"(a) : "l"(p));
    return a;
}
#define SWZ128(off) ((off) ^ (((off) >> 3) & 0x70))

__device__ __forceinline__ void cp16(uint32_t s, const void* g) {
    asm volatile("cp.async.cg.shared.global [%0], [%1], 16;" :: "r"(s), "l"(g));
}
#define CP_COMMIT() asm volatile("cp.async.commit_group;" ::: "memory")
#define CP_WAIT0()  asm volatile("cp.async.wait_group 0;" ::: "memory")
#define CP_WAIT1()  asm volatile("cp.async.wait_group 1;" ::: "memory")

__device__ __forceinline__ void ldsm_x4(uint32_t* r, uint32_t addr) {
    asm volatile("ldmatrix.sync.aligned.m8n8.x4.shared.b16 {%0,%1,%2,%3}, [%4];"
                 : "=r"(r[0]), "=r"(r[1]), "=r"(r[2]), "=r"(r[3]) : "r"(addr));
}

__device__ __forceinline__ void mma_bf16(float* d, const uint32_t* a, const uint32_t* b) {
    asm volatile(
        "mma.sync.aligned.m16n8k16.row.col.f32.bf16.bf16.f32 "
        "{%0,%1,%2,%3}, {%4,%5,%6,%7}, {%8,%9}, {%0,%1,%2,%3};"
        : "+f"(d[0]), "+f"(d[1]), "+f"(d[2]), "+f"(d[3])
        : "r"(a[0]), "r"(a[1]), "r"(a[2]), "r"(a[3]), "r"(b[0]), "r"(b[1]));
}

__device__ __forceinline__ uint32_t pack_hi(float a, float b) {
    __nv_bfloat162 h;
    h.x = __float2bfloat16(a);
    h.y = __float2bfloat16(b);
    return *(uint32_t*)&h;
}
__device__ __forceinline__ uint32_t pack_lo(float a, float b, uint32_t hw) {
    __nv_bfloat162 h = *(__nv_bfloat162*)&hw;
    __nv_bfloat162 l;
    l.x = __float2bfloat16(a - __bfloat162float(h.x));
    l.y = __float2bfloat16(b - __bfloat162float(h.y));
    return *(uint32_t*)&l;
}

// =====================================================================
// permutation build (counting sort by head id / tail id)
// =====================================================================
__global__ __launch_bounds__(256) void zero_hist(int* hist) {
    const int i = blockIdx.x * 256 + threadIdx.x;
    if (i < 2 * N_OBJ) hist[i] = 0;
}

__global__ __launch_bounds__(256) void build_hist(
    const int* __restrict__ pair_idx, int* hist)
{
    const int r = blockIdx.x * 256 + threadIdx.x;
    if (r >= N_REL) return;
    atomicAdd(&hist[pair_idx[2 * r]], 1);
    atomicAdd(&hist[N_OBJ + pair_idx[2 * r + 1]], 1);
}

// exclusive scan of both 1280-bins halves; 1 block, 256 threads
__global__ __launch_bounds__(256) void scan_hist(
    const int* __restrict__ hist, int* offs)
{
    __shared__ int ps[256];
    const int tid = threadIdx.x;
    for (int half = 0; half < 2; half++) {
        const int base = half * N_OBJ;
        int v[5];
        int sum = 0;
        #pragma unroll
        for (int s = 0; s < 5; s++) {
            v[s] = hist[base + tid * 5 + s];
            sum += v[s];
        }
        ps[tid] = sum;
        __syncthreads();
        // inclusive Hillis-Steele over 256 partials
        #pragma unroll
        for (int d = 1; d < 256; d <<= 1) {
            int t = (tid >= d) ? ps[tid - d] : 0;
            __syncthreads();
            ps[tid] += t;
            __syncthreads();
        }
        int run = (tid == 0) ? 0 : ps[tid - 1];
        #pragma unroll
        for (int s = 0; s < 5; s++) {
            offs[base + tid * 5 + s] = run;
            run += v[s];
        }
        __syncthreads();
    }
}

__global__ __launch_bounds__(256) void scatter_perm(
    const int* __restrict__ pair_idx, int* offs, int* perm)
{
    const int r = blockIdx.x * 256 + threadIdx.x;
    if (r >= N_REL) return;
    const int h = pair_idx[2 * r];
    const int t = pair_idx[2 * r + 1];
    const int p0 = atomicAdd(&offs[h], 1);
    perm[p0] = r;
    const int p1 = atomicAdd(&offs[N_OBJ + t], 1);
    perm[N_REL + p1] = r;
}

// =====================================================================
// preprocessing
// =====================================================================
__global__ __launch_bounds__(256) void split_simple(
    const float* __restrict__ src, __nv_bfloat16* __restrict__ hi,
    __nv_bfloat16* __restrict__ lo, int n)
{
    int i = blockIdx.x * 256 + threadIdx.x;
    if (i >= n) return;
    float x = src[i];
    __nv_bfloat16 h = __float2bfloat16(x);
    hi[i] = h;
    lo[i] = __float2bfloat16(x - __bfloat162float(h));
}

__global__ __launch_bounds__(256) void transpose_split(
    const float* __restrict__ W, int R, int C,
    __nv_bfloat16* __restrict__ bhi, __nv_bfloat16* __restrict__ blo)
{
    __shared__ float t[32][33];
    const int kb = blockIdx.y * 32;
    const int nb = blockIdx.x * 32;
    const int tx = threadIdx.x & 31;
    const int ty = threadIdx.x >> 5;
    #pragma unroll
    for (int s = 0; s < 4; s++)
        t[ty + s * 8][tx] = W[(size_t)(kb + ty + s * 8) * C + nb + tx];
    __syncthreads();
    #pragma unroll
    for (int s = 0; s < 4; s++) {
        const int n = nb + ty + s * 8;
        const float x = t[tx][ty + s * 8];
        __nv_bfloat16 h = __float2bfloat16(x);
        const size_t o = (size_t)n * R + kb + tx;
        bhi[o] = h;
        blo[o] = __float2bfloat16(x - __bfloat162float(h));
    }
}

__global__ __launch_bounds__(256) void transpose_split_Wrel(
    const float* __restrict__ Wr,
    __nv_bfloat16* __restrict__ whi, __nv_bfloat16* __restrict__ wlo)
{
    __shared__ float t[32][33];
    const int kb = blockIdx.y * 32;
    const int nb = blockIdx.x * 32;
    const int tx = threadIdx.x & 31;
    const int ty = threadIdx.x >> 5;
    #pragma unroll
    for (int s = 0; s < 4; s++) {
        const int k = kb + ty + s * 8;
        const int n = nb + tx;
        t[ty + s * 8][tx] = (n < NUM_REL_CLS) ? Wr[(size_t)k * NUM_REL_CLS + n] : 0.0f;
    }
    __syncthreads();
    #pragma unroll
    for (int s = 0; s < 4; s++) {
        const int n = nb + ty + s * 8;
        const float x = t[tx][ty + s * 8];
        __nv_bfloat16 h = __float2bfloat16(x);
        const size_t o = (size_t)n * POOL + kb + tx;
        whi[o] = h;
        wlo[o] = __float2bfloat16(x - __bfloat162float(h));
    }
}

// =====================================================================
// K1 via HMMA (R10/R11 proven)
// =====================================================================
__global__ __launch_bounds__(256) void k1_hmma(
    const __nv_bfloat16* __restrict__ Ahi, const __nv_bfloat16* __restrict__ Alo,
    const __nv_bfloat16* __restrict__ Bhi, const __nv_bfloat16* __restrict__ Blo,
    const float* __restrict__ bias,
    __nv_bfloat16* __restrict__ Ohi, __nv_bfloat16* __restrict__ Olo)
{
    extern __shared__ char smem[];
    const uint32_t sb = smem_u32(smem);
    const int tid = threadIdx.x;
    const int wid = tid >> 5;
    const int lane = tid & 31;
    const int bx = blockIdx.x;
    const int by = blockIdx.y;
    const int NCH = HID / K2_BK;

    const int m0 = (wid >> 1) * 32;
    const int n0 = (wid & 1) * 32;

    float acc[2][4][4];
    #pragma unroll
    for (int mf = 0; mf < 2; mf++)
        #pragma unroll
        for (int nf = 0; nf < 4; nf++)
            #pragma unroll
            for (int e = 0; e < 4; e++) acc[mf][nf][e] = 0.0f;

    const int aRowOff = (m0 + (lane & 15)) * 128 + ((lane & 16) ? 16 : 0);
    const int bRowOff = (n0 + (lane & 7) + ((lane & 16) ? 8 : 0)) * 128 + ((lane & 8) ? 16 : 0);

    auto STAGE = [&](int ch, int stg) {
        const int k0 = ch * K2_BK;
        const uint32_t base = sb + stg * K2_STAGE;
        #pragma unroll
        for (int it = 0; it < 4; it++) {
            const int g = tid + it * 256;
            const int row = g >> 3, grp = g & 7;
            const size_t src = (size_t)(by * 128 + row) * HID + k0 + grp * 8;
            const uint32_t off = SWZ128((uint32_t)(row * 128 + grp * 16));
            cp16(base + S_AHI + off, Ahi + src);
            cp16(base + S_ALO + off, Alo + src);
        }
        #pragma unroll
        for (int it = 0; it < 2; it++) {
            const int g = tid + it * 256;
            const int row = g >> 3, grp = g & 7;
            const size_t src = (size_t)(bx * 64 + row) * HID + k0 + grp * 8;
            const uint32_t off = SWZ128((uint32_t)(row * 128 + grp * 16));
            cp16(base + S_BHI + off, Bhi + src);
            cp16(base + S_BLO + off, Blo + src);
        }
        CP_COMMIT();
    };

    STAGE(0, 0);
    int buf = 0;
    for (int ch = 0; ch < NCH; ch++) {
        const bool nxt = (ch + 1) < NCH;
        if (nxt) STAGE(ch + 1, buf ^ 1);
        if (nxt) CP_WAIT1(); else CP_WAIT0();
        __syncthreads();

        const uint32_t base = sb + buf * K2_STAGE;
        #pragma unroll
        for (int kk = 0; kk < K2_BK; kk += 16) {
            uint32_t ahi[2][4], alo[2][4], bh[2][4], bl[2][4];
            #pragma unroll
            for (int mf = 0; mf < 2; mf++) {
                const uint32_t off = SWZ128((uint32_t)(aRowOff + mf * 16 * 128 + kk * 2));
                ldsm_x4(ahi[mf], base + S_AHI + off);
                ldsm_x4(alo[mf], base + S_ALO + off);
            }
            #pragma unroll
            for (int nf2 = 0; nf2 < 2; nf2++) {
                const uint32_t off = SWZ128((uint32_t)(bRowOff + nf2 * 16 * 128 + kk * 2));
                ldsm_x4(bh[nf2], base + S_BHI + off);
                ldsm_x4(bl[nf2], base + S_BLO + off);
            }
            #pragma unroll
            for (int mf = 0; mf < 2; mf++) {
                #pragma unroll
                for (int nf = 0; nf < 4; nf++) {
                    const uint32_t* bhp = &bh[nf >> 1][(nf & 1) * 2];
                    const uint32_t* blp = &bl[nf >> 1][(nf & 1) * 2];
                    mma_bf16(acc[mf][nf], ahi[mf], bhp);
                    mma_bf16(acc[mf][nf], ahi[mf], blp);
                    mma_bf16(acc[mf][nf], alo[mf], bhp);
                }
            }
        }
        __syncthreads();
        buf ^= 1;
    }

    const int gm = by * 128 + m0 + (lane >> 2);
    const int gn = bx * 64 + n0 + (lane & 3) * 2;
    #pragma unroll
    for (int mf = 0; mf < 2; mf++) {
        #pragma unroll
        for (int nf = 0; nf < 4; nf++) {
            const int col = gn + nf * 8;
            const float b0 = bias[col], b1 = bias[col + 1];
            const int r0 = gm + mf * 16;
            float v0x = acc[mf][nf][0] + b0, v0y = acc[mf][nf][1] + b1;
            float v1x = acc[mf][nf][2] + b0, v1y = acc[mf][nf][3] + b1;
            uint32_t h0 = pack_hi(v0x, v0y), l0 = pack_lo(v0x, v0y, h0);
            uint32_t h1 = pack_hi(v1x, v1y), l1 = pack_lo(v1x, v1y, h1);
            *(uint32_t*)&Ohi[(size_t)r0 * (2 * HID) + col] = h0;
            *(uint32_t*)&Olo[(size_t)r0 * (2 * HID) + col] = l0;
            *(uint32_t*)&Ohi[(size_t)(r0 + 8) * (2 * HID) + col] = h1;
            *(uint32_t*)&Olo[(size_t)(r0 + 8) * (2 * HID) + col] = l1;
        }
    }
}

// =====================================================================
// K2 via HMMA (R11 proven body; nBase selects the POOL column half)
// =====================================================================
__global__ __launch_bounds__(256) void k2_hmma(
    const __nv_bfloat16* __restrict__ Ahi, const __nv_bfloat16* __restrict__ Alo,
    const __nv_bfloat16* __restrict__ Bhi, const __nv_bfloat16* __restrict__ Blo,
    const float* __restrict__ bpc,
    float* __restrict__ hc, float* __restrict__ tcat, int nBase)
{
    extern __shared__ char smem[];
    const uint32_t sb = smem_u32(smem);
    const int tid = threadIdx.x;
    const int wid = tid >> 5;
    const int lane = tid & 31;
    const int bx = blockIdx.x + nBase;
    const int by = blockIdx.y;
    const int z = blockIdx.z;
    const int koff = z * HID;
    const int NCH = HID / K2_BK;

    const int m0 = (wid >> 1) * 32;
    const int n0 = (wid & 1) * 32;

    float acc[2][4][4];
    #pragma unroll
    for (int mf = 0; mf < 2; mf++)
        #pragma unroll
        for (int nf = 0; nf < 4; nf++)
            #pragma unroll
            for (int e = 0; e < 4; e++) acc[mf][nf][e] = 0.0f;

    const int aRowOff = (m0 + (lane & 15)) * 128 + ((lane & 16) ? 16 : 0);
    const int bRowOff = (n0 + (lane & 7) + ((lane & 16) ? 8 : 0)) * 128 + ((lane & 8) ? 16 : 0);

    auto STAGE = [&](int ch, int stg) {
        const int k0 = koff + ch * K2_BK;
        const uint32_t base = sb + stg * K2_STAGE;
        #pragma unroll
        for (int it = 0; it < 4; it++) {
            const int g = tid + it * 256;
            const int row = g >> 3, grp = g & 7;
            const size_t src = (size_t)(by * 128 + row) * (2 * HID) + k0 + grp * 8;
            const uint32_t off = SWZ128((uint32_t)(row * 128 + grp * 16));
            cp16(base + S_AHI + off, Ahi + src);
            cp16(base + S_ALO + off, Alo + src);
        }
        #pragma unroll
        for (int it = 0; it < 2; it++) {
            const int g = tid + it * 256;
            const int row = g >> 3, grp = g & 7;
            const size_t src = (size_t)(bx * 64 + row) * (2 * HID) + k0 + grp * 8;
            const uint32_t off = SWZ128((uint32_t)(row * 128 + grp * 16));
            cp16(base + S_BHI + off, Bhi + src);
            cp16(base + S_BLO + off, Blo + src);
        }
        CP_COMMIT();
    };

    STAGE(0, 0);
    int buf = 0;
    for (int ch = 0; ch < NCH; ch++) {
        const bool nxt = (ch + 1) < NCH;
        if (nxt) STAGE(ch + 1, buf ^ 1);
        if (nxt) CP_WAIT1(); else CP_WAIT0();
        __syncthreads();

        const uint32_t base = sb + buf * K2_STAGE;
        #pragma unroll
        for (int kk = 0; kk < K2_BK; kk += 16) {
            uint32_t ahi[2][4], alo[2][4], bh[2][4], bl[2][4];
            #pragma unroll
            for (int mf = 0; mf < 2; mf++) {
                const uint32_t off = SWZ128((uint32_t)(aRowOff + mf * 16 * 128 + kk * 2));
                ldsm_x4(ahi[mf], base + S_AHI + off);
                ldsm_x4(alo[mf], base + S_ALO + off);
            }
            #pragma unroll
            for (int nf2 = 0; nf2 < 2; nf2++) {
                const uint32_t off = SWZ128((uint32_t)(bRowOff + nf2 * 16 * 128 + kk * 2));
                ldsm_x4(bh[nf2], base + S_BHI + off);
                ldsm_x4(bl[nf2], base + S_BLO + off);
            }
            #pragma unroll
            for (int mf = 0; mf < 2; mf++) {
                #pragma unroll
                for (int nf = 0; nf < 4; nf++) {
                    const uint32_t* bhp = &bh[nf >> 1][(nf & 1) * 2];
                    const uint32_t* blp = &bl[nf >> 1][(nf & 1) * 2];
                    mma_bf16(acc[mf][nf], ahi[mf], bhp);
                    mma_bf16(acc[mf][nf], ahi[mf], blp);
                    mma_bf16(acc[mf][nf], alo[mf], bhp);
                }
            }
        }
        __syncthreads();
        buf ^= 1;
    }

    const int gm = by * 128 + m0 + (lane >> 2);
    const int gn = bx * 64 + n0 + (lane & 3) * 2;
    float* Cb = (z == 0 ? hc : tcat);
    #pragma unroll
    for (int mf = 0; mf < 2; mf++) {
        #pragma unroll
        for (int nf = 0; nf < 4; nf++) {
            const int col = gn + nf * 8;
            float b0 = 0.0f, b1 = 0.0f;
            if (z == 0) { b0 = bpc[col]; b1 = bpc[col + 1]; }
            const int r0 = gm + mf * 16;
            float2 v0, v1;
            v0.x = acc[mf][nf][0] + b0;
            v0.y = acc[mf][nf][1] + b1;
            v1.x = acc[mf][nf][2] + b0;
            v1.y = acc[mf][nf][3] + b1;
            *(float2*)&Cb[(size_t)r0 * POOL + col] = v0;
            *(float2*)&Cb[(size_t)(r0 + 8) * POOL + col] = v1;
        }
    }
}

// =====================================================================
// K3 via HMMA (R11 body + relation permutation for gather locality)
// =====================================================================
__global__ __launch_bounds__(256, 2) void k3_hmma(
    const float* __restrict__ U,
    const float* __restrict__ HC,
    const float* __restrict__ TC,
    const __nv_bfloat16* __restrict__ Whi,
    const __nv_bfloat16* __restrict__ Wlo,
    const int* __restrict__ pair_idx,
    const int* __restrict__ perm,
    float* __restrict__ part, int sp)
{
    extern __shared__ char smem[];
    const uint32_t sb = smem_u32(smem);
    const int tid = threadIdx.x;
    const int wid = tid >> 5;
    const int lane = tid & 31;
    const int rBase = blockIdx.x * R3_M;
    const int kb = sp * R3_KS;

    const int m0 = (wid >> 2) * 32;
    const int n0 = (wid & 3) * 16;

    const int sRow = tid >> 2;
    const int sK = (tid & 3) * 16;
    const int grow = perm[rBase + sRow];      // permuted relation id
    const int si = pair_idx[2 * grow];
    const int sj = pair_idx[2 * grow + 1];
    const float* hp = HC + (size_t)si * POOL + kb + sK;
    const float* tp = TC + (size_t)sj * POOL + kb + sK;
    const float* up = U  + (size_t)grow * POOL + kb + sK;
    const int sgrp = (tid & 3) * 2;

    float4 ru[4], rh[4], rt[4];

    auto PRELOAD = [&](int ch) {
        #pragma unroll
        for (int s = 0; s < 4; s++) {
            ru[s] = *(const float4*)(up + ch * R3_BK + s * 4);
            rh[s] = *(const float4*)(hp + ch * R3_BK + s * 4);
            rt[s] = *(const float4*)(tp + ch * R3_BK + s * 4);
        }
    };
    auto ASTORE = [&](int stg) {
        float mv[16];
        #pragma unroll
        for (int s = 0; s < 4; s++) {
            mv[s * 4 + 0] = (rh[s].x + rt[s].x) * ru[s].x;
            mv[s * 4 + 1] = (rh[s].y + rt[s].y) * ru[s].y;
            mv[s * 4 + 2] = (rh[s].z + rt[s].z) * ru[s].z;
            mv[s * 4 + 3] = (rh[s].w + rt[s].w) * ru[s].w;
        }
        #pragma unroll
        for (int g2 = 0; g2 < 2; g2++) {
            uint4 hw, lw;
            uint32_t* hp4 = (uint32_t*)&hw;
            uint32_t* lp4 = (uint32_t*)&lw;
            #pragma unroll
            for (int p = 0; p < 4; p++) {
                const float a = mv[g2 * 8 + p * 2];
                const float b = mv[g2 * 8 + p * 2 + 1];
                hp4[p] = pack_hi(a, b);
                lp4[p] = pack_lo(a, b, hp4[p]);
            }
            const uint32_t dst = SWZ128((uint32_t)(sRow * 128 + (sgrp + g2) * 16));
            *(uint4*)(smem + stg * R3_STAGE + R3_AHI + dst) = hw;
            *(uint4*)(smem + stg * R3_STAGE + R3_ALO + dst) = lw;
        }
    };
    auto BSTAGE = [&](int ch, int stg) {
        const uint32_t base = sb + stg * R3_STAGE;
        #pragma unroll
        for (int it = 0; it < 2; it++) {
            const int g = tid + it * 256;
            const int row = g >> 3, grp = g & 7;
            const size_t src = (size_t)row * POOL + kb + ch * R3_BK + grp * 8;
            const uint32_t off = SWZ128((uint32_t)(row * 128 + grp * 16));
            cp16(base + R3_BHI + off, Whi + src);
            cp16(base + R3_BLO + off, Wlo + src);
        }
        CP_COMMIT();
    };

    float acc[2][2][4];
    #pragma unroll
    for (int mf = 0; mf < 2; mf++)
        #pragma unroll
        for (int nf = 0; nf < 2; nf++)
            #pragma unroll
            for (int e = 0; e < 4; e++) acc[mf][nf][e] = 0.0f;

    const int aRowOff = (m0 + (lane & 15)) * 128 + ((lane & 16) ? 16 : 0);
    const int bRowOff = (n0 + (lane & 7) + ((lane & 16) ? 8 : 0)) * 128 + ((lane & 8) ? 16 : 0);

    PRELOAD(0);
    ASTORE(0);
    BSTAGE(0, 0);
    BSTAGE(1, 1);

    int buf = 0;
    for (int ch = 0; ch < R3_NCH; ch++) {
        const bool nxt = (ch + 1) < R3_NCH;
        if (nxt) CP_WAIT1(); else CP_WAIT0();
        __syncthreads();

        if (nxt) PRELOAD(ch + 1);

        const uint32_t base = sb + buf * R3_STAGE;
        #pragma unroll
        for (int kk = 0; kk < R3_BK; kk += 16) {
            uint32_t ahi[2][4], alo[2][4], bh[4], bl[4];
            #pragma unroll
            for (int mf = 0; mf < 2; mf++) {
                const uint32_t off = SWZ128((uint32_t)(aRowOff + mf * 16 * 128 + kk * 2));
                ldsm_x4(ahi[mf], base + R3_AHI + off);
                ldsm_x4(alo[mf], base + R3_ALO + off);
            }
            {
                const uint32_t off = SWZ128((uint32_t)(bRowOff + kk * 2));
                ldsm_x4(bh, base + R3_BHI + off);
                ldsm_x4(bl, base + R3_BLO + off);
            }
            #pragma unroll
            for (int mf = 0; mf < 2; mf++) {
                #pragma unroll
                for (int nf = 0; nf < 2; nf++) {
                    const uint32_t* bhp = &bh[nf * 2];
                    const uint32_t* blp = &bl[nf * 2];
                    mma_bf16(acc[mf][nf], ahi[mf], bhp);
                    mma_bf16(acc[mf][nf], ahi[mf], blp);
                    mma_bf16(acc[mf][nf], alo[mf], bhp);
                }
            }
        }
        __syncthreads();

        if (nxt) {
            ASTORE(buf ^ 1);
            if (ch + 2 < R3_NCH) BSTAGE(ch + 2, buf);
        }
        buf ^= 1;
    }

    // epilogue: rows mapped through perm back to original relation ids
    const int lrow = m0 + (lane >> 2);
    const int gn = n0 + (lane & 3) * 2;
    float* pb = part + (size_t)sp * N_REL * NPAD;
    #pragma unroll
    for (int mf = 0; mf < 2; mf++) {
        const int row0 = perm[rBase + lrow + mf * 16];
        const int row1 = perm[rBase + lrow + mf * 16 + 8];
        #pragma unroll
        for (int nf = 0; nf < 2; nf++) {
            const int col = gn + nf * 8;
            float2 v0, v1;
            v0.x = acc[mf][nf][0];
            v0.y = acc[mf][nf][1];
            v1.x = acc[mf][nf][2];
            v1.y = acc[mf][nf][3];
            *(float2*)&pb[(size_t)row0 * NPAD + col] = v0;
            *(float2*)&pb[(size_t)row1 * NPAD + col] = v1;
        }
    }
}

// =====================================================================
// combine
// =====================================================================
__global__ __launch_bounds__(256) void combine_rel(
    const float* __restrict__ part,
    const float* __restrict__ br,
    const float* __restrict__ freq,
    const int* __restrict__ pair_idx,
    const int* __restrict__ obj_preds,
    float* __restrict__ out)
{
    const int r = blockIdx.x * 4 + (threadIdx.x >> 6);
    const int c = threadIdx.x & 63;
    if (c >= NUM_REL_CLS) return;

    const int bi = obj_preds[pair_idx[2 * r]] * NUM_OBJ_CLS
                 + obj_preds[pair_idx[2 * r + 1]];
    float s = 0.0f;
    #pragma unroll
    for (int sp = 0; sp < R3_SPLITK; sp++)
        s += part[((size_t)sp * N_REL + r) * NPAD + c];
    out[(size_t)r * NUM_REL_CLS + c] = s + br[c] + freq[(size_t)bi * NUM_REL_CLS + c];
}

// =====================================================================
// Launch (R15 fork structure + permutation build on s2)
// =====================================================================
extern "C" void kernel_launch(void* const* d_in, const int* in_sizes, int n_in,
                              void* d_out, int out_size)
{
    const float* edge_ctx   = (const float*)d_in[0];
    const float* U          = (const float*)d_in[1];
    const float* W_post_emb = (const float*)d_in[2];
    const float* b_post_emb = (const float*)d_in[3];
    const float* W_post_cat = (const float*)d_in[4];
    const float* b_post_cat = (const float*)d_in[5];
    const float* W_rel      = (const float*)d_in[6];
    const float* b_rel      = (const float*)d_in[7];
    const float* freq       = (const float*)d_in[8];
    const int*   pair_idx   = (const int*)d_in[9];
    const int*   obj_preds  = (const int*)d_in[10];
    float* out = (float*)d_out;

    float *hc, *tc, *part;
    __nv_bfloat16 *ahi, *alo, *bhi, *blo, *whi, *wlo, *echi, *eclo, *wehi, *welo;
    int *hist, *offs, *perm;
    cudaGetSymbolAddress((void**)&hc, g_head_cat);
    cudaGetSymbolAddress((void**)&tc, g_tail_cat);
    cudaGetSymbolAddress((void**)&part, g_part);
    cudaGetSymbolAddress((void**)&ahi, g_A_hi);
    cudaGetSymbolAddress((void**)&alo, g_A_lo);
    cudaGetSymbolAddress((void**)&bhi, g_Bt_hi);
    cudaGetSymbolAddress((void**)&blo, g_Bt_lo);
    cudaGetSymbolAddress((void**)&whi, g_Wt_hi);
    cudaGetSymbolAddress((void**)&wlo, g_Wt_lo);
    cudaGetSymbolAddress((void**)&echi, g_Ec_hi);
    cudaGetSymbolAddress((void**)&eclo, g_Ec_lo);
    cudaGetSymbolAddress((void**)&wehi, g_We_hi);
    cudaGetSymbolAddress((void**)&welo, g_We_lo);
    cudaGetSymbolAddress((void**)&hist, g_hist);
    cudaGetSymbolAddress((void**)&offs, g_offs);
    cudaGetSymbolAddress((void**)&perm, g_perm);

    static bool init_done = false;
    static cudaStream_t s2;
    static cudaEvent_t ev0, eB, eL, eH, e3;
    if (!init_done) {
        cudaFuncSetAttribute(k1_hmma, cudaFuncAttributeMaxDynamicSharedMemorySize,
                             2 * K2_STAGE);
        cudaFuncSetAttribute(k2_hmma, cudaFuncAttributeMaxDynamicSharedMemorySize,
                             2 * K2_STAGE);
        cudaFuncSetAttribute(k3_hmma, cudaFuncAttributeMaxDynamicSharedMemorySize,
                             2 * R3_STAGE);
        cudaStreamCreateWithFlags(&s2, cudaStreamNonBlocking);
        cudaEventCreateWithFlags(&ev0, cudaEventDisableTiming);
        cudaEventCreateWithFlags(&eB, cudaEventDisableTiming);
        cudaEventCreateWithFlags(&eL, cudaEventDisableTiming);
        cudaEventCreateWithFlags(&eH, cudaEventDisableTiming);
        cudaEventCreateWithFlags(&e3, cudaEventDisableTiming);
        init_done = true;
    }

    cudaEventRecord(ev0, 0);
    cudaStreamWaitEvent(s2, ev0, 0);

    // s2: weight prep (needed by K2 soonest)
    transpose_split_Wrel<<<dim3(NPAD / 32, POOL / 32), 256, 0, s2>>>(W_rel, whi, wlo);
    transpose_split<<<dim3(POOL / 32, (2 * HID) / 32), 256, 0, s2>>>(
        W_post_cat, 2 * HID, POOL, bhi, blo);
    cudaEventRecord(eB, s2);

    // s2: relation permutations (needed only by K3, later on s2)
    zero_hist<<<10, 256, 0, s2>>>(hist);
    build_hist<<<N_REL / 256, 256, 0, s2>>>(pair_idx, hist);
    scan_hist<<<1, 256, 0, s2>>>(hist, offs);
    scatter_perm<<<N_REL / 256, 256, 0, s2>>>(pair_idx, offs, perm);

    // s0: edge_ctx/W_post_emb prep and K1
    split_simple<<<(N_OBJ * HID + 255) / 256, 256>>>(edge_ctx, echi, eclo, N_OBJ * HID);
    transpose_split<<<dim3((2 * HID) / 32, HID / 32), 256>>>(
        W_post_emb, HID, 2 * HID, wehi, welo);
    k1_hmma<<<dim3((2 * HID) / 64, N_OBJ / 128), 256, 2 * K2_STAGE>>>(
        echi, eclo, wehi, welo, b_post_emb, ahi, alo);

    // s0: K2 halves
    cudaStreamWaitEvent(0, eB, 0);
    k2_hmma<<<dim3(32, N_OBJ / 128, 2), 256, 2 * K2_STAGE>>>(
        ahi, alo, bhi, blo, b_post_cat, hc, tc, 0);
    cudaEventRecord(eL, 0);
    k2_hmma<<<dim3(32, N_OBJ / 128, 2), 256, 2 * K2_STAGE>>>(
        ahi, alo, bhi, blo, b_post_cat, hc, tc, 32);
    cudaEventRecord(eH, 0);

    // s2: K3 sp0 (head-sorted perm), sp1 (tail-sorted perm)
    cudaStreamWaitEvent(s2, eL, 0);
    k3_hmma<<<dim3(N_REL / R3_M), 256, 2 * R3_STAGE, s2>>>(
        U, hc, tc, whi, wlo, pair_idx, perm, part, 0);
    cudaStreamWaitEvent(s2, eH, 0);
    k3_hmma<<<dim3(N_REL / R3_M), 256, 2 * R3_STAGE, s2>>>(
        U, hc, tc, whi, wlo, pair_idx, perm + N_REL, part, 1);
    cudaEventRecord(e3, s2);

    // s0: join and combine
    cudaStreamWaitEvent(0, e3, 0);
    combine_rel<<<N_REL / 4, 256>>>(part, b_rel, freq, pair_idx, obj_preds, out);
}

// round 17
// speedup vs baseline: 1.2989x; 1.0075x over previous
#include <cuda_runtime.h>
#include <cuda_bf16.h>
#include <cstdint>

#define HID 512
#define POOL 4096
#define N_OBJ 1280
#define N_REL 16384
#define NUM_OBJ_CLS 151
#define NUM_REL_CLS 51
#define NPAD 64

// K3 tiling (R11 proven config)
#define R3_M 64
#define R3_BK 64
#define R3_SPLITK 2
#define R3_KS (POOL / R3_SPLITK)   // 2048
#define R3_NCH (R3_KS / R3_BK)     // 32
#define R3_STAGE 32768
#define R3_AHI 0
#define R3_ALO 8192
#define R3_BHI 16384
#define R3_BLO 24576

// K2/K1 hmma tiling (R11 proven config)
#define K2_BK 64
#define K2_STAGE 49152
#define S_AHI 0
#define S_ALO 16384
#define S_BHI 32768
#define S_BLO 40960

// -------- scratch (device globals; no allocation allowed) --------
__device__ float g_head_cat[N_OBJ * POOL];
__device__ float g_tail_cat[N_OBJ * POOL];
__device__ float g_part[N_REL * NPAD];                    // sp0 partials only
__device__ __nv_bfloat16 g_A_hi[N_OBJ * 2 * HID];
__device__ __nv_bfloat16 g_A_lo[N_OBJ * 2 * HID];
__device__ __nv_bfloat16 g_Bt_hi[POOL * 2 * HID];
__device__ __nv_bfloat16 g_Bt_lo[POOL * 2 * HID];
__device__ __nv_bfloat16 g_Wt_hi[NPAD * POOL];
__device__ __nv_bfloat16 g_Wt_lo[NPAD * POOL];
__device__ __nv_bfloat16 g_Ec_hi[N_OBJ * HID];
__device__ __nv_bfloat16 g_Ec_lo[N_OBJ * HID];
__device__ __nv_bfloat16 g_We_hi[(2 * HID) * HID];
__device__ __nv_bfloat16 g_We_lo[(2 * HID) * HID];
__device__ int g_hist[2 * N_OBJ];
__device__ int g_offs[2 * N_OBJ];
__device__ int g_perm[2 * N_REL];

// =====================================================================
// helpers
// =====================================================================
__device__ __forceinline__ uint32_t smem_u32(const void* p) {
    uint32_t a;
    asm("{ .reg .u64 t; cvta.to.shared.u64 t, %1; cvt.u32.u64 %0, t; }"
        : "=r"(a) : "l"(p));
    return a;
}
#define SWZ128(off) ((off) ^ (((off) >> 3) & 0x70))

__device__ __forceinline__ void cp16(uint32_t s, const void* g) {
    asm volatile("cp.async.cg.shared.global [%0], [%1], 16;" :: "r"(s), "l"(g));
}
#define CP_COMMIT() asm volatile("cp.async.commit_group;" ::: "memory")
#define CP_WAIT0()  asm volatile("cp.async.wait_group 0;" ::: "memory")
#define CP_WAIT1()  asm volatile("cp.async.wait_group 1;" ::: "memory")

__device__ __forceinline__ void ldsm_x4(uint32_t* r, uint32_t addr) {
    asm volatile("ldmatrix.sync.aligned.m8n8.x4.shared.b16 {%0,%1,%2,%3}, [%4];"
                 : "=r"(r[0]), "=r"(r[1]), "=r"(r[2]), "=r"(r[3]) : "r"(addr));
}

__device__ __forceinline__ void mma_bf16(float* d, const uint32_t* a, const uint32_t* b) {
    asm volatile(
        "mma.sync.aligned.m16n8k16.row.col.f32.bf16.bf16.f32 "
        "{%0,%1,%2,%3}, {%4,%5,%6,%7}, {%8,%9}, {%0,%1,%2,%3};"
        : "+f"(d[0]), "+f"(d[1]), "+f"(d[2]), "+f"(d[3])
        : "r"(a[0]), "r"(a[1]), "r"(a[2]), "r"(a[3]), "r"(b[0]), "r"(b[1]));
}

__device__ __forceinline__ uint32_t pack_hi(float a, float b) {
    __nv_bfloat162 h;
    h.x = __float2bfloat16(a);
    h.y = __float2bfloat16(b);
    return *(uint32_t*)&h;
}
__device__ __forceinline__ uint32_t pack_lo(float a, float b, uint32_t hw) {
    __nv_bfloat162 h = *(__nv_bfloat162*)&hw;
    __nv_bfloat162 l;
    l.x = __float2bfloat16(a - __bfloat162float(h.x));
    l.y = __float2bfloat16(b - __bfloat162float(h.y));
    return *(uint32_t*)&l;
}

// =====================================================================
// permutation build (counting sort by head / tail id)
// =====================================================================
__global__ __launch_bounds__(256) void zero_hist(int* hist) {
    const int i = blockIdx.x * 256 + threadIdx.x;
    if (i < 2 * N_OBJ) hist[i] = 0;
}

__global__ __launch_bounds__(256) void build_hist(
    const int* __restrict__ pair_idx, int* hist)
{
    const int r = blockIdx.x * 256 + threadIdx.x;
    if (r >= N_REL) return;
    atomicAdd(&hist[pair_idx[2 * r]], 1);
    atomicAdd(&hist[N_OBJ + pair_idx[2 * r + 1]], 1);
}

__global__ __launch_bounds__(256) void scan_hist(
    const int* __restrict__ hist, int* offs)
{
    __shared__ int ps[256];
    const int tid = threadIdx.x;
    for (int half = 0; half < 2; half++) {
        const int base = half * N_OBJ;
        int v[5];
        int sum = 0;
        #pragma unroll
        for (int s = 0; s < 5; s++) {
            v[s] = hist[base + tid * 5 + s];
            sum += v[s];
        }
        ps[tid] = sum;
        __syncthreads();
        #pragma unroll
        for (int d = 1; d < 256; d <<= 1) {
            int t = (tid >= d) ? ps[tid - d] : 0;
            __syncthreads();
            ps[tid] += t;
            __syncthreads();
        }
        int run = (tid == 0) ? 0 : ps[tid - 1];
        #pragma unroll
        for (int s = 0; s < 5; s++) {
            offs[base + tid * 5 + s] = run;
            run += v[s];
        }
        __syncthreads();
    }
}

__global__ __launch_bounds__(256) void scatter_perm(
    const int* __restrict__ pair_idx, int* offs, int* perm)
{
    const int r = blockIdx.x * 256 + threadIdx.x;
    if (r >= N_REL) return;
    const int h = pair_idx[2 * r];
    const int t = pair_idx[2 * r + 1];
    const int p0 = atomicAdd(&offs[h], 1);
    perm[p0] = r;
    const int p1 = atomicAdd(&offs[N_OBJ + t], 1);
    perm[N_REL + p1] = r;
}

// =====================================================================
// preprocessing
// =====================================================================
__global__ __launch_bounds__(256) void split_simple(
    const float* __restrict__ src, __nv_bfloat16* __restrict__ hi,
    __nv_bfloat16* __restrict__ lo, int n)
{
    int i = blockIdx.x * 256 + threadIdx.x;
    if (i >= n) return;
    float x = src[i];
    __nv_bfloat16 h = __float2bfloat16(x);
    hi[i] = h;
    lo[i] = __float2bfloat16(x - __bfloat162float(h));
}

__global__ __launch_bounds__(256) void transpose_split(
    const float* __restrict__ W, int R, int C,
    __nv_bfloat16* __restrict__ bhi, __nv_bfloat16* __restrict__ blo)
{
    __shared__ float t[32][33];
    const int kb = blockIdx.y * 32;
    const int nb = blockIdx.x * 32;
    const int tx = threadIdx.x & 31;
    const int ty = threadIdx.x >> 5;
    #pragma unroll
    for (int s = 0; s < 4; s++)
        t[ty + s * 8][tx] = W[(size_t)(kb + ty + s * 8) * C + nb + tx];
    __syncthreads();
    #pragma unroll
    for (int s = 0; s < 4; s++) {
        const int n = nb + ty + s * 8;
        const float x = t[tx][ty + s * 8];
        __nv_bfloat16 h = __float2bfloat16(x);
        const size_t o = (size_t)n * R + kb + tx;
        bhi[o] = h;
        blo[o] = __float2bfloat16(x - __bfloat162float(h));
    }
}

__global__ __launch_bounds__(256) void transpose_split_Wrel(
    const float* __restrict__ Wr,
    __nv_bfloat16* __restrict__ whi, __nv_bfloat16* __restrict__ wlo)
{
    __shared__ float t[32][33];
    const int kb = blockIdx.y * 32;
    const int nb = blockIdx.x * 32;
    const int tx = threadIdx.x & 31;
    const int ty = threadIdx.x >> 5;
    #pragma unroll
    for (int s = 0; s < 4; s++) {
        const int k = kb + ty + s * 8;
        const int n = nb + tx;
        t[ty + s * 8][tx] = (n < NUM_REL_CLS) ? Wr[(size_t)k * NUM_REL_CLS + n] : 0.0f;
    }
    __syncthreads();
    #pragma unroll
    for (int s = 0; s < 4; s++) {
        const int n = nb + ty + s * 8;
        const float x = t[tx][ty + s * 8];
        __nv_bfloat16 h = __float2bfloat16(x);
        const size_t o = (size_t)n * POOL + kb + tx;
        whi[o] = h;
        wlo[o] = __float2bfloat16(x - __bfloat162float(h));
    }
}

// =====================================================================
// K1 via HMMA (frozen)
// =====================================================================
__global__ __launch_bounds__(256) void k1_hmma(
    const __nv_bfloat16* __restrict__ Ahi, const __nv_bfloat16* __restrict__ Alo,
    const __nv_bfloat16* __restrict__ Bhi, const __nv_bfloat16* __restrict__ Blo,
    const float* __restrict__ bias,
    __nv_bfloat16* __restrict__ Ohi, __nv_bfloat16* __restrict__ Olo)
{
    extern __shared__ char smem[];
    const uint32_t sb = smem_u32(smem);
    const int tid = threadIdx.x;
    const int wid = tid >> 5;
    const int lane = tid & 31;
    const int bx = blockIdx.x;
    const int by = blockIdx.y;
    const int NCH = HID / K2_BK;

    const int m0 = (wid >> 1) * 32;
    const int n0 = (wid & 1) * 32;

    float acc[2][4][4];
    #pragma unroll
    for (int mf = 0; mf < 2; mf++)
        #pragma unroll
        for (int nf = 0; nf < 4; nf++)
            #pragma unroll
            for (int e = 0; e < 4; e++) acc[mf][nf][e] = 0.0f;

    const int aRowOff = (m0 + (lane & 15)) * 128 + ((lane & 16) ? 16 : 0);
    const int bRowOff = (n0 + (lane & 7) + ((lane & 16) ? 8 : 0)) * 128 + ((lane & 8) ? 16 : 0);

    auto STAGE = [&](int ch, int stg) {
        const int k0 = ch * K2_BK;
        const uint32_t base = sb + stg * K2_STAGE;
        #pragma unroll
        for (int it = 0; it < 4; it++) {
            const int g = tid + it * 256;
            const int row = g >> 3, grp = g & 7;
            const size_t src = (size_t)(by * 128 + row) * HID + k0 + grp * 8;
            const uint32_t off = SWZ128((uint32_t)(row * 128 + grp * 16));
            cp16(base + S_AHI + off, Ahi + src);
            cp16(base + S_ALO + off, Alo + src);
        }
        #pragma unroll
        for (int it = 0; it < 2; it++) {
            const int g = tid + it * 256;
            const int row = g >> 3, grp = g & 7;
            const size_t src = (size_t)(bx * 64 + row) * HID + k0 + grp * 8;
            const uint32_t off = SWZ128((uint32_t)(row * 128 + grp * 16));
            cp16(base + S_BHI + off, Bhi + src);
            cp16(base + S_BLO + off, Blo + src);
        }
        CP_COMMIT();
    };

    STAGE(0, 0);
    int buf = 0;
    for (int ch = 0; ch < NCH; ch++) {
        const bool nxt = (ch + 1) < NCH;
        if (nxt) STAGE(ch + 1, buf ^ 1);
        if (nxt) CP_WAIT1(); else CP_WAIT0();
        __syncthreads();

        const uint32_t base = sb + buf * K2_STAGE;
        #pragma unroll
        for (int kk = 0; kk < K2_BK; kk += 16) {
            uint32_t ahi[2][4], alo[2][4], bh[2][4], bl[2][4];
            #pragma unroll
            for (int mf = 0; mf < 2; mf++) {
                const uint32_t off = SWZ128((uint32_t)(aRowOff + mf * 16 * 128 + kk * 2));
                ldsm_x4(ahi[mf], base + S_AHI + off);
                ldsm_x4(alo[mf], base + S_ALO + off);
            }
            #pragma unroll
            for (int nf2 = 0; nf2 < 2; nf2++) {
                const uint32_t off = SWZ128((uint32_t)(bRowOff + nf2 * 16 * 128 + kk * 2));
                ldsm_x4(bh[nf2], base + S_BHI + off);
                ldsm_x4(bl[nf2], base + S_BLO + off);
            }
            #pragma unroll
            for (int mf = 0; mf < 2; mf++) {
                #pragma unroll
                for (int nf = 0; nf < 4; nf++) {
                    const uint32_t* bhp = &bh[nf >> 1][(nf & 1) * 2];
                    const uint32_t* blp = &bl[nf >> 1][(nf & 1) * 2];
                    mma_bf16(acc[mf][nf], ahi[mf], bhp);
                    mma_bf16(acc[mf][nf], ahi[mf], blp);
                    mma_bf16(acc[mf][nf], alo[mf], bhp);
                }
            }
        }
        __syncthreads();
        buf ^= 1;
    }

    const int gm = by * 128 + m0 + (lane >> 2);
    const int gn = bx * 64 + n0 + (lane & 3) * 2;
    #pragma unroll
    for (int mf = 0; mf < 2; mf++) {
        #pragma unroll
        for (int nf = 0; nf < 4; nf++) {
            const int col = gn + nf * 8;
            const float b0 = bias[col], b1 = bias[col + 1];
            const int r0 = gm + mf * 16;
            float v0x = acc[mf][nf][0] + b0, v0y = acc[mf][nf][1] + b1;
            float v1x = acc[mf][nf][2] + b0, v1y = acc[mf][nf][3] + b1;
            uint32_t h0 = pack_hi(v0x, v0y), l0 = pack_lo(v0x, v0y, h0);
            uint32_t h1 = pack_hi(v1x, v1y), l1 = pack_lo(v1x, v1y, h1);
            *(uint32_t*)&Ohi[(size_t)r0 * (2 * HID) + col] = h0;
            *(uint32_t*)&Olo[(size_t)r0 * (2 * HID) + col] = l0;
            *(uint32_t*)&Ohi[(size_t)(r0 + 8) * (2 * HID) + col] = h1;
            *(uint32_t*)&Olo[(size_t)(r0 + 8) * (2 * HID) + col] = l1;
        }
    }
}

// =====================================================================
// K2 via HMMA (frozen; nBase selects POOL column half)
// =====================================================================
__global__ __launch_bounds__(256) void k2_hmma(
    const __nv_bfloat16* __restrict__ Ahi, const __nv_bfloat16* __restrict__ Alo,
    const __nv_bfloat16* __restrict__ Bhi, const __nv_bfloat16* __restrict__ Blo,
    const float* __restrict__ bpc,
    float* __restrict__ hc, float* __restrict__ tcat, int nBase)
{
    extern __shared__ char smem[];
    const uint32_t sb = smem_u32(smem);
    const int tid = threadIdx.x;
    const int wid = tid >> 5;
    const int lane = tid & 31;
    const int bx = blockIdx.x + nBase;
    const int by = blockIdx.y;
    const int z = blockIdx.z;
    const int koff = z * HID;
    const int NCH = HID / K2_BK;

    const int m0 = (wid >> 1) * 32;
    const int n0 = (wid & 1) * 32;

    float acc[2][4][4];
    #pragma unroll
    for (int mf = 0; mf < 2; mf++)
        #pragma unroll
        for (int nf = 0; nf < 4; nf++)
            #pragma unroll
            for (int e = 0; e < 4; e++) acc[mf][nf][e] = 0.0f;

    const int aRowOff = (m0 + (lane & 15)) * 128 + ((lane & 16) ? 16 : 0);
    const int bRowOff = (n0 + (lane & 7) + ((lane & 16) ? 8 : 0)) * 128 + ((lane & 8) ? 16 : 0);

    auto STAGE = [&](int ch, int stg) {
        const int k0 = koff + ch * K2_BK;
        const uint32_t base = sb + stg * K2_STAGE;
        #pragma unroll
        for (int it = 0; it < 4; it++) {
            const int g = tid + it * 256;
            const int row = g >> 3, grp = g & 7;
            const size_t src = (size_t)(by * 128 + row) * (2 * HID) + k0 + grp * 8;
            const uint32_t off = SWZ128((uint32_t)(row * 128 + grp * 16));
            cp16(base + S_AHI + off, Ahi + src);
            cp16(base + S_ALO + off, Alo + src);
        }
        #pragma unroll
        for (int it = 0; it < 2; it++) {
            const int g = tid + it * 256;
            const int row = g >> 3, grp = g & 7;
            const size_t src = (size_t)(bx * 64 + row) * (2 * HID) + k0 + grp * 8;
            const uint32_t off = SWZ128((uint32_t)(row * 128 + grp * 16));
            cp16(base + S_BHI + off, Bhi + src);
            cp16(base + S_BLO + off, Blo + src);
        }
        CP_COMMIT();
    };

    STAGE(0, 0);
    int buf = 0;
    for (int ch = 0; ch < NCH; ch++) {
        const bool nxt = (ch + 1) < NCH;
        if (nxt) STAGE(ch + 1, buf ^ 1);
        if (nxt) CP_WAIT1(); else CP_WAIT0();
        __syncthreads();

        const uint32_t base = sb + buf * K2_STAGE;
        #pragma unroll
        for (int kk = 0; kk < K2_BK; kk += 16) {
            uint32_t ahi[2][4], alo[2][4], bh[2][4], bl[2][4];
            #pragma unroll
            for (int mf = 0; mf < 2; mf++) {
                const uint32_t off = SWZ128((uint32_t)(aRowOff + mf * 16 * 128 + kk * 2));
                ldsm_x4(ahi[mf], base + S_AHI + off);
                ldsm_x4(alo[mf], base + S_ALO + off);
            }
            #pragma unroll
            for (int nf2 = 0; nf2 < 2; nf2++) {
                const uint32_t off = SWZ128((uint32_t)(bRowOff + nf2 * 16 * 128 + kk * 2));
                ldsm_x4(bh[nf2], base + S_BHI + off);
                ldsm_x4(bl[nf2], base + S_BLO + off);
            }
            #pragma unroll
            for (int mf = 0; mf < 2; mf++) {
                #pragma unroll
                for (int nf = 0; nf < 4; nf++) {
                    const uint32_t* bhp = &bh[nf >> 1][(nf & 1) * 2];
                    const uint32_t* blp = &bl[nf >> 1][(nf & 1) * 2];
                    mma_bf16(acc[mf][nf], ahi[mf], bhp);
                    mma_bf16(acc[mf][nf], ahi[mf], blp);
                    mma_bf16(acc[mf][nf], alo[mf], bhp);
                }
            }
        }
        __syncthreads();
        buf ^= 1;
    }

    const int gm = by * 128 + m0 + (lane >> 2);
    const int gn = bx * 64 + n0 + (lane & 3) * 2;
    float* Cb = (z == 0 ? hc : tcat);
    #pragma unroll
    for (int mf = 0; mf < 2; mf++) {
        #pragma unroll
        for (int nf = 0; nf < 4; nf++) {
            const int col = gn + nf * 8;
            float b0 = 0.0f, b1 = 0.0f;
            if (z == 0) { b0 = bpc[col]; b1 = bpc[col + 1]; }
            const int r0 = gm + mf * 16;
            float2 v0, v1;
            v0.x = acc[mf][nf][0] + b0;
            v0.y = acc[mf][nf][1] + b1;
            v1.x = acc[mf][nf][2] + b0;
            v1.y = acc[mf][nf][3] + b1;
            *(float2*)&Cb[(size_t)r0 * POOL + col] = v0;
            *(float2*)&Cb[(size_t)(r0 + 8) * POOL + col] = v1;
        }
    }
}

// =====================================================================
// K3 via HMMA (R16 body). final==0: write partials for rows.
// final==1: fused epilogue — read sp0 partial, add bias + freq, write out.
// =====================================================================
__global__ __launch_bounds__(256, 2) void k3_hmma(
    const float* __restrict__ U,
    const float* __restrict__ HC,
    const float* __restrict__ TC,
    const __nv_bfloat16* __restrict__ Whi,
    const __nv_bfloat16* __restrict__ Wlo,
    const int* __restrict__ pair_idx,
    const int* __restrict__ perm,
    float* __restrict__ part,
    const float* __restrict__ br,
    const float* __restrict__ freq,
    const int* __restrict__ obj_preds,
    float* __restrict__ out,
    int sp, int final_pass)
{
    extern __shared__ char smem[];
    const uint32_t sb = smem_u32(smem);
    const int tid = threadIdx.x;
    const int wid = tid >> 5;
    const int lane = tid & 31;
    const int rBase = blockIdx.x * R3_M;
    const int kb = sp * R3_KS;

    const int m0 = (wid >> 2) * 32;
    const int n0 = (wid & 3) * 16;

    const int sRow = tid >> 2;
    const int sK = (tid & 3) * 16;
    const int grow = perm[rBase + sRow];
    const int si = pair_idx[2 * grow];
    const int sj = pair_idx[2 * grow + 1];
    const float* hp = HC + (size_t)si * POOL + kb + sK;
    const float* tp = TC + (size_t)sj * POOL + kb + sK;
    const float* up = U  + (size_t)grow * POOL + kb + sK;
    const int sgrp = (tid & 3) * 2;

    float4 ru[4], rh[4], rt[4];

    auto PRELOAD = [&](int ch) {
        #pragma unroll
        for (int s = 0; s < 4; s++) {
            ru[s] = *(const float4*)(up + ch * R3_BK + s * 4);
            rh[s] = *(const float4*)(hp + ch * R3_BK + s * 4);
            rt[s] = *(const float4*)(tp + ch * R3_BK + s * 4);
        }
    };
    auto ASTORE = [&](int stg) {
        float mv[16];
        #pragma unroll
        for (int s = 0; s < 4; s++) {
            mv[s * 4 + 0] = (rh[s].x + rt[s].x) * ru[s].x;
            mv[s * 4 + 1] = (rh[s].y + rt[s].y) * ru[s].y;
            mv[s * 4 + 2] = (rh[s].z + rt[s].z) * ru[s].z;
            mv[s * 4 + 3] = (rh[s].w + rt[s].w) * ru[s].w;
        }
        #pragma unroll
        for (int g2 = 0; g2 < 2; g2++) {
            uint4 hw, lw;
            uint32_t* hp4 = (uint32_t*)&hw;
            uint32_t* lp4 = (uint32_t*)&lw;
            #pragma unroll
            for (int p = 0; p < 4; p++) {
                const float a = mv[g2 * 8 + p * 2];
                const float b = mv[g2 * 8 + p * 2 + 1];
                hp4[p] = pack_hi(a, b);
                lp4[p] = pack_lo(a, b, hp4[p]);
            }
            const uint32_t dst = SWZ128((uint32_t)(sRow * 128 + (sgrp + g2) * 16));
            *(uint4*)(smem + stg * R3_STAGE + R3_AHI + dst) = hw;
            *(uint4*)(smem + stg * R3_STAGE + R3_ALO + dst) = lw;
        }
    };
    auto BSTAGE = [&](int ch, int stg) {
        const uint32_t base = sb + stg * R3_STAGE;
        #pragma unroll
        for (int it = 0; it < 2; it++) {
            const int g = tid + it * 256;
            const int row = g >> 3, grp = g & 7;
            const size_t src = (size_t)row * POOL + kb + ch * R3_BK + grp * 8;
            const uint32_t off = SWZ128((uint32_t)(row * 128 + grp * 16));
            cp16(base + R3_BHI + off, Whi + src);
            cp16(base + R3_BLO + off, Wlo + src);
        }
        CP_COMMIT();
    };

    float acc[2][2][4];
    #pragma unroll
    for (int mf = 0; mf < 2; mf++)
        #pragma unroll
        for (int nf = 0; nf < 2; nf++)
            #pragma unroll
            for (int e = 0; e < 4; e++) acc[mf][nf][e] = 0.0f;

    const int aRowOff = (m0 + (lane & 15)) * 128 + ((lane & 16) ? 16 : 0);
    const int bRowOff = (n0 + (lane & 7) + ((lane & 16) ? 8 : 0)) * 128 + ((lane & 8) ? 16 : 0);

    PRELOAD(0);
    ASTORE(0);
    BSTAGE(0, 0);
    BSTAGE(1, 1);

    int buf = 0;
    for (int ch = 0; ch < R3_NCH; ch++) {
        const bool nxt = (ch + 1) < R3_NCH;
        if (nxt) CP_WAIT1(); else CP_WAIT0();
        __syncthreads();

        if (nxt) PRELOAD(ch + 1);

        const uint32_t base = sb + buf * R3_STAGE;
        #pragma unroll
        for (int kk = 0; kk < R3_BK; kk += 16) {
            uint32_t ahi[2][4], alo[2][4], bh[4], bl[4];
            #pragma unroll
            for (int mf = 0; mf < 2; mf++) {
                const uint32_t off = SWZ128((uint32_t)(aRowOff + mf * 16 * 128 + kk * 2));
                ldsm_x4(ahi[mf], base + R3_AHI + off);
                ldsm_x4(alo[mf], base + R3_ALO + off);
            }
            {
                const uint32_t off = SWZ128((uint32_t)(bRowOff + kk * 2));
                ldsm_x4(bh, base + R3_BHI + off);
                ldsm_x4(bl, base + R3_BLO + off);
            }
            #pragma unroll
            for (int mf = 0; mf < 2; mf++) {
                #pragma unroll
                for (int nf = 0; nf < 2; nf++) {
                    const uint32_t* bhp = &bh[nf * 2];
                    const uint32_t* blp = &bl[nf * 2];
                    mma_bf16(acc[mf][nf], ahi[mf], bhp);
                    mma_bf16(acc[mf][nf], ahi[mf], blp);
                    mma_bf16(acc[mf][nf], alo[mf], bhp);
                }
            }
        }
        __syncthreads();

        if (nxt) {
            ASTORE(buf ^ 1);
            if (ch + 2 < R3_NCH) BSTAGE(ch + 2, buf);
        }
        buf ^= 1;
    }

    const int lrow = m0 + (lane >> 2);
    const int gn = n0 + (lane & 3) * 2;

    if (!final_pass) {
        #pragma unroll
        for (int mf = 0; mf < 2; mf++) {
            const int row0 = perm[rBase + lrow + mf * 16];
            const int row1 = perm[rBase + lrow + mf * 16 + 8];
            #pragma unroll
            for (int nf = 0; nf < 2; nf++) {
                const int col = gn + nf * 8;
                float2 v0, v1;
                v0.x = acc[mf][nf][0];
                v0.y = acc[mf][nf][1];
                v1.x = acc[mf][nf][2];
                v1.y = acc[mf][nf][3];
                *(float2*)&part[(size_t)row0 * NPAD + col] = v0;
                *(float2*)&part[(size_t)row1 * NPAD + col] = v1;
            }
        }
    } else {
        // fused combine: out[r,c] = acc + part0[r,c] + br[c] + freq[bi,c]
        #pragma unroll
        for (int mf = 0; mf < 2; mf++) {
            #pragma unroll
            for (int half = 0; half < 2; half++) {
                const int r = perm[rBase + lrow + mf * 16 + half * 8];
                const int bi = obj_preds[pair_idx[2 * r]] * NUM_OBJ_CLS
                             + obj_preds[pair_idx[2 * r + 1]];
                const float* fq = freq + (size_t)bi * NUM_REL_CLS;
                float* orow = out + (size_t)r * NUM_REL_CLS;
                const float* prow = part + (size_t)r * NPAD;
                #pragma unroll
                for (int nf = 0; nf < 2; nf++) {
                    const int col = gn + nf * 8;
                    const float a0 = acc[mf][nf][half * 2 + 0];
                    const float a1 = acc[mf][nf][half * 2 + 1];
                    if (col < NUM_REL_CLS)
                        orow[col] = a0 + prow[col] + br[col] + fq[col];
                    if (col + 1 < NUM_REL_CLS)
                        orow[col + 1] = a1 + prow[col + 1] + br[col + 1] + fq[col + 1];
                }
            }
        }
    }
}

// =====================================================================
// Launch (R16 fork structure; combine fused into K3 sp1)
// =====================================================================
extern "C" void kernel_launch(void* const* d_in, const int* in_sizes, int n_in,
                              void* d_out, int out_size)
{
    const float* edge_ctx   = (const float*)d_in[0];
    const float* U          = (const float*)d_in[1];
    const float* W_post_emb = (const float*)d_in[2];
    const float* b_post_emb = (const float*)d_in[3];
    const float* W_post_cat = (const float*)d_in[4];
    const float* b_post_cat = (const float*)d_in[5];
    const float* W_rel      = (const float*)d_in[6];
    const float* b_rel      = (const float*)d_in[7];
    const float* freq       = (const float*)d_in[8];
    const int*   pair_idx   = (const int*)d_in[9];
    const int*   obj_preds  = (const int*)d_in[10];
    float* out = (float*)d_out;

    float *hc, *tc, *part;
    __nv_bfloat16 *ahi, *alo, *bhi, *blo, *whi, *wlo, *echi, *eclo, *wehi, *welo;
    int *hist, *offs, *perm;
    cudaGetSymbolAddress((void**)&hc, g_head_cat);
    cudaGetSymbolAddress((void**)&tc, g_tail_cat);
    cudaGetSymbolAddress((void**)&part, g_part);
    cudaGetSymbolAddress((void**)&ahi, g_A_hi);
    cudaGetSymbolAddress((void**)&alo, g_A_lo);
    cudaGetSymbolAddress((void**)&bhi, g_Bt_hi);
    cudaGetSymbolAddress((void**)&blo, g_Bt_lo);
    cudaGetSymbolAddress((void**)&whi, g_Wt_hi);
    cudaGetSymbolAddress((void**)&wlo, g_Wt_lo);
    cudaGetSymbolAddress((void**)&echi, g_Ec_hi);
    cudaGetSymbolAddress((void**)&eclo, g_Ec_lo);
    cudaGetSymbolAddress((void**)&wehi, g_We_hi);
    cudaGetSymbolAddress((void**)&welo, g_We_lo);
    cudaGetSymbolAddress((void**)&hist, g_hist);
    cudaGetSymbolAddress((void**)&offs, g_offs);
    cudaGetSymbolAddress((void**)&perm, g_perm);

    static bool init_done = false;
    static cudaStream_t s2;
    static cudaEvent_t ev0, eB, eL, eH, e3;
    if (!init_done) {
        cudaFuncSetAttribute(k1_hmma, cudaFuncAttributeMaxDynamicSharedMemorySize,
                             2 * K2_STAGE);
        cudaFuncSetAttribute(k2_hmma, cudaFuncAttributeMaxDynamicSharedMemorySize,
                             2 * K2_STAGE);
        cudaFuncSetAttribute(k3_hmma, cudaFuncAttributeMaxDynamicSharedMemorySize,
                             2 * R3_STAGE);
        cudaStreamCreateWithFlags(&s2, cudaStreamNonBlocking);
        cudaEventCreateWithFlags(&ev0, cudaEventDisableTiming);
        cudaEventCreateWithFlags(&eB, cudaEventDisableTiming);
        cudaEventCreateWithFlags(&eL, cudaEventDisableTiming);
        cudaEventCreateWithFlags(&eH, cudaEventDisableTiming);
        cudaEventCreateWithFlags(&e3, cudaEventDisableTiming);
        init_done = true;
    }

    cudaEventRecord(ev0, 0);
    cudaStreamWaitEvent(s2, ev0, 0);

    // s2: weight prep
    transpose_split_Wrel<<<dim3(NPAD / 32, POOL / 32), 256, 0, s2>>>(W_rel, whi, wlo);
    transpose_split<<<dim3(POOL / 32, (2 * HID) / 32), 256, 0, s2>>>(
        W_post_cat, 2 * HID, POOL, bhi, blo);
    cudaEventRecord(eB, s2);

    // s2: relation permutations
    zero_hist<<<10, 256, 0, s2>>>(hist);
    build_hist<<<N_REL / 256, 256, 0, s2>>>(pair_idx, hist);
    scan_hist<<<1, 256, 0, s2>>>(hist, offs);
    scatter_perm<<<N_REL / 256, 256, 0, s2>>>(pair_idx, offs, perm);

    // s0: edge_ctx/W_post_emb prep and K1
    split_simple<<<(N_OBJ * HID + 255) / 256, 256>>>(edge_ctx, echi, eclo, N_OBJ * HID);
    transpose_split<<<dim3((2 * HID) / 32, HID / 32), 256>>>(
        W_post_emb, HID, 2 * HID, wehi, welo);
    k1_hmma<<<dim3((2 * HID) / 64, N_OBJ / 128), 256, 2 * K2_STAGE>>>(
        echi, eclo, wehi, welo, b_post_emb, ahi, alo);

    // s0: K2 halves
    cudaStreamWaitEvent(0, eB, 0);
    k2_hmma<<<dim3(32, N_OBJ / 128, 2), 256, 2 * K2_STAGE>>>(
        ahi, alo, bhi, blo, b_post_cat, hc, tc, 0);
    cudaEventRecord(eL, 0);
    k2_hmma<<<dim3(32, N_OBJ / 128, 2), 256, 2 * K2_STAGE>>>(
        ahi, alo, bhi, blo, b_post_cat, hc, tc, 32);
    cudaEventRecord(eH, 0);

    // s2: K3 sp0 (partials), then sp1 (fused final epilogue -> out)
    cudaStreamWaitEvent(s2, eL, 0);
    k3_hmma<<<dim3(N_REL / R3_M), 256, 2 * R3_STAGE, s2>>>(
        U, hc, tc, whi, wlo, pair_idx, perm, part,
        b_rel, freq, obj_preds, out, 0, 0);
    cudaStreamWaitEvent(s2, eH, 0);
    k3_hmma<<<dim3(N_REL / R3_M), 256, 2 * R3_STAGE, s2>>>(
        U, hc, tc, whi, wlo, pair_idx, perm + N_REL, part,
        b_rel, freq, obj_preds, out, 1, 1);
    cudaEventRecord(e3, s2);

    // s0: join (out produced on s2)
    cudaStreamWaitEvent(0, e3, 0);
}